// round 2
// baseline (speedup 1.0000x reference)
#include <cuda_runtime.h>
#include <math.h>

#define SEQ    2048
#define HID    2048
#define NHEADS 16
#define DH     128
#define ATT_SCALE 0.08838834764831845f   // 1/sqrt(128)

// ---------------- scratch (device globals: allocation-free) ----------------
__device__ float g_q[SEQ * HID];
__device__ float g_k[SEQ * HID];
__device__ float g_v[SEQ * HID];
__device__ float g_attn[SEQ * HID];
__device__ float g_o[SEQ * HID];

// ====================================================================
// GEMM: C[M,N] = A[M,K] @ B[N,K]^T + bias[N]   (M=N=K=2048)
// 128x128 block tile, BK=8, 256 threads, 8x8 register tile per thread.
// ====================================================================
__global__ __launch_bounds__(256) void sgemm_nt_bias(
    const float* __restrict__ A, const float* __restrict__ B,
    const float* __restrict__ bias, float* __restrict__ C)
{
    const int K = HID, N = HID;
    __shared__ float As[8][132];
    __shared__ float Bs[8][132];

    const int tid = threadIdx.x;
    const int bm = blockIdx.y * 128;
    const int bn = blockIdx.x * 128;
    const int tr = tid >> 4;        // 0..15 (row group)
    const int tc = tid & 15;        // 0..15 (col group)
    const int lr = tid >> 1;        // 0..127 load row
    const int lc = (tid & 1) << 2;  // 0 or 4 load col

    const float* Ap = A + (bm + lr) * K + lc;
    const float* Bp = B + (bn + lr) * K + lc;

    float acc[8][8];
#pragma unroll
    for (int i = 0; i < 8; i++)
#pragma unroll
        for (int j = 0; j < 8; j++) acc[i][j] = 0.f;

    for (int k0 = 0; k0 < K; k0 += 8) {
        float4 av = *(const float4*)(Ap + k0);
        float4 bv = *(const float4*)(Bp + k0);
        As[lc + 0][lr] = av.x; As[lc + 1][lr] = av.y;
        As[lc + 2][lr] = av.z; As[lc + 3][lr] = av.w;
        Bs[lc + 0][lr] = bv.x; Bs[lc + 1][lr] = bv.y;
        Bs[lc + 2][lr] = bv.z; Bs[lc + 3][lr] = bv.w;
        __syncthreads();
#pragma unroll
        for (int kk = 0; kk < 8; kk++) {
            float a[8], b[8];
            float4 t0 = *(const float4*)&As[kk][tr * 8];
            float4 t1 = *(const float4*)&As[kk][tr * 8 + 4];
            a[0] = t0.x; a[1] = t0.y; a[2] = t0.z; a[3] = t0.w;
            a[4] = t1.x; a[5] = t1.y; a[6] = t1.z; a[7] = t1.w;
            float4 u0 = *(const float4*)&Bs[kk][tc * 8];
            float4 u1 = *(const float4*)&Bs[kk][tc * 8 + 4];
            b[0] = u0.x; b[1] = u0.y; b[2] = u0.z; b[3] = u0.w;
            b[4] = u1.x; b[5] = u1.y; b[6] = u1.z; b[7] = u1.w;
#pragma unroll
            for (int i = 0; i < 8; i++)
#pragma unroll
                for (int j = 0; j < 8; j++)
                    acc[i][j] = fmaf(a[i], b[j], acc[i][j]);
        }
        __syncthreads();
    }

    float bb[8];
#pragma unroll
    for (int j = 0; j < 8; j++) bb[j] = bias[bn + tc * 8 + j];

#pragma unroll
    for (int i = 0; i < 8; i++) {
        const int row = bm + tr * 8 + i;
        float* Cp = C + row * N + bn + tc * 8;
        float4 o0, o1;
        o0.x = acc[i][0] + bb[0]; o0.y = acc[i][1] + bb[1];
        o0.z = acc[i][2] + bb[2]; o0.w = acc[i][3] + bb[3];
        o1.x = acc[i][4] + bb[4]; o1.y = acc[i][5] + bb[5];
        o1.z = acc[i][6] + bb[6]; o1.w = acc[i][7] + bb[7];
        *(float4*)Cp = o0;
        *(float4*)(Cp + 4) = o1;
    }
}

// ====================================================================
// RoPE on q and k in place. One block per sequence position, 1024
// threads = 16 heads * 64 rotation pairs.
// Matches reference rounding: inv_freq (fp32), ang = s*inv_freq (fp32),
// then cos/sin evaluated in double and cast to fp32.
// ====================================================================
__global__ __launch_bounds__(1024) void rope_kernel(float* __restrict__ q,
                                                    float* __restrict__ k)
{
    const int s = blockIdx.x;
    const int t = threadIdx.x;
    const int h = t >> 6;       // head 0..15
    const int i = t & 63;       // pair 0..63

    const float invf = (float)pow(10000.0, -(double)(2 * i) / 128.0);
    const float ang  = (float)s * invf;
    const float c  = (float)cos((double)ang);
    const float sn = (float)sin((double)ang);

    const int base = s * HID + h * DH + i;
    float a = q[base], b = q[base + 64];
    q[base]      = a * c - b * sn;
    q[base + 64] = b * c + a * sn;
    a = k[base];  b = k[base + 64];
    k[base]      = a * c - b * sn;
    k[base + 64] = b * c + a * sn;
}

// ====================================================================
// Flash attention (fp32, causal). Block = (q-tile 64 rows, one head).
// 256 threads = 16x16: each thread owns 4 score rows x 4 score cols,
// and 4 rows x 8 cols of the output accumulator.
// ====================================================================
__global__ __launch_bounds__(256) void flash_kernel(
    const float* __restrict__ Qg, const float* __restrict__ Kg,
    const float* __restrict__ Vg, float* __restrict__ Og)
{
    extern __shared__ float sm[];
    float* sQ = sm;              // 64 x 132
    float* sK = sQ + 64 * 132;   // 64 x 132
    float* sV = sK + 64 * 132;   // 64 x 132
    float* sP = sV + 64 * 132;   // 64 x 68

    const int h  = blockIdx.y;
    const int q0 = blockIdx.x * 64;
    const int tid = threadIdx.x;
    const int tr = tid >> 4;     // 0..15 -> rows tr*4 .. tr*4+3
    const int tc = tid & 15;     // 0..15 -> score cols tc*4.., O cols tc*8..

    // load Q tile
    for (int idx = tid; idx < 64 * 32; idx += 256) {
        const int r = idx >> 5;
        const int c = (idx & 31) << 2;
        *(float4*)&sQ[r * 132 + c] =
            *(const float4*)(Qg + (q0 + r) * HID + h * DH + c);
    }

    float m_i[4], l_i[4], oacc[4][8];
#pragma unroll
    for (int i = 0; i < 4; i++) {
        m_i[i] = -1e30f; l_i[i] = 0.f;
#pragma unroll
        for (int c = 0; c < 8; c++) oacc[i][c] = 0.f;
    }
    __syncthreads();

    const int ntiles = (q0 >> 6) + 1;
    for (int t = 0; t < ntiles; t++) {
        const int j0 = t << 6;
        // load K,V tiles
        for (int idx = tid; idx < 64 * 32; idx += 256) {
            const int r = idx >> 5;
            const int c = (idx & 31) << 2;
            *(float4*)&sK[r * 132 + c] =
                *(const float4*)(Kg + (j0 + r) * HID + h * DH + c);
            *(float4*)&sV[r * 132 + c] =
                *(const float4*)(Vg + (j0 + r) * HID + h * DH + c);
        }
        __syncthreads();

        // scores S = Q K^T (4x4 per thread), d vectorized by 4
        float sc[4][4];
#pragma unroll
        for (int i = 0; i < 4; i++)
#pragma unroll
            for (int j = 0; j < 4; j++) sc[i][j] = 0.f;

        for (int d = 0; d < DH; d += 4) {
            float4 qv[4], kv[4];
#pragma unroll
            for (int i = 0; i < 4; i++)
                qv[i] = *(const float4*)&sQ[(tr * 4 + i) * 132 + d];
#pragma unroll
            for (int j = 0; j < 4; j++)
                kv[j] = *(const float4*)&sK[(tc * 4 + j) * 132 + d];
#pragma unroll
            for (int i = 0; i < 4; i++)
#pragma unroll
                for (int j = 0; j < 4; j++) {
                    sc[i][j] = fmaf(qv[i].x, kv[j].x, sc[i][j]);
                    sc[i][j] = fmaf(qv[i].y, kv[j].y, sc[i][j]);
                    sc[i][j] = fmaf(qv[i].z, kv[j].z, sc[i][j]);
                    sc[i][j] = fmaf(qv[i].w, kv[j].w, sc[i][j]);
                }
        }

        // scale + causal mask (only diagonal tile needs masking)
        const bool diag = (j0 == q0);
#pragma unroll
        for (int i = 0; i < 4; i++) {
            const int gr = tr * 4 + i;
#pragma unroll
            for (int j = 0; j < 4; j++) {
                sc[i][j] *= ATT_SCALE;
                if (diag && (tc * 4 + j > gr)) sc[i][j] = -1e30f;
            }
        }

        // online softmax, per row
#pragma unroll
        for (int i = 0; i < 4; i++) {
            float mx = fmaxf(fmaxf(sc[i][0], sc[i][1]), fmaxf(sc[i][2], sc[i][3]));
#pragma unroll
            for (int off = 8; off >= 1; off >>= 1)
                mx = fmaxf(mx, __shfl_xor_sync(0xffffffffu, mx, off));
            const float mnew  = fmaxf(m_i[i], mx);
            const float alpha = __expf(m_i[i] - mnew);
            float rs = 0.f;
#pragma unroll
            for (int j = 0; j < 4; j++) {
                sc[i][j] = __expf(sc[i][j] - mnew);
                rs += sc[i][j];
            }
#pragma unroll
            for (int off = 8; off >= 1; off >>= 1)
                rs += __shfl_xor_sync(0xffffffffu, rs, off);
            l_i[i] = l_i[i] * alpha + rs;
            m_i[i] = mnew;
#pragma unroll
            for (int c = 0; c < 8; c++) oacc[i][c] *= alpha;
            float* pp = &sP[(tr * 4 + i) * 68 + tc * 4];
            pp[0] = sc[i][0]; pp[1] = sc[i][1];
            pp[2] = sc[i][2]; pp[3] = sc[i][3];
        }
        __syncthreads();

        // O += P @ V
        for (int j = 0; j < 64; j++) {
            const float4 v0 = *(const float4*)&sV[j * 132 + tc * 8];
            const float4 v1 = *(const float4*)&sV[j * 132 + tc * 8 + 4];
#pragma unroll
            for (int i = 0; i < 4; i++) {
                const float p = sP[(tr * 4 + i) * 68 + j];
                oacc[i][0] = fmaf(p, v0.x, oacc[i][0]);
                oacc[i][1] = fmaf(p, v0.y, oacc[i][1]);
                oacc[i][2] = fmaf(p, v0.z, oacc[i][2]);
                oacc[i][3] = fmaf(p, v0.w, oacc[i][3]);
                oacc[i][4] = fmaf(p, v1.x, oacc[i][4]);
                oacc[i][5] = fmaf(p, v1.y, oacc[i][5]);
                oacc[i][6] = fmaf(p, v1.z, oacc[i][6]);
                oacc[i][7] = fmaf(p, v1.w, oacc[i][7]);
            }
        }
        __syncthreads();
    }

    // epilogue: normalize and write
#pragma unroll
    for (int i = 0; i < 4; i++) {
        const float inv = 1.f / l_i[i];
        float4 o0, o1;
        o0.x = oacc[i][0] * inv; o0.y = oacc[i][1] * inv;
        o0.z = oacc[i][2] * inv; o0.w = oacc[i][3] * inv;
        o1.x = oacc[i][4] * inv; o1.y = oacc[i][5] * inv;
        o1.z = oacc[i][6] * inv; o1.w = oacc[i][7] * inv;
        float* Op = Og + (q0 + tr * 4 + i) * HID + h * DH + tc * 8;
        *(float4*)Op = o0;
        *(float4*)(Op + 4) = o1;
    }
}

// ====================================================================
// Residual + LayerNorm. One block per row.
// ====================================================================
__device__ __forceinline__ float block_sum256(float v, float* red)
{
    __syncthreads();
    const int lane = threadIdx.x & 31;
    const int wp   = threadIdx.x >> 5;
#pragma unroll
    for (int o = 16; o; o >>= 1) v += __shfl_xor_sync(0xffffffffu, v, o);
    if (lane == 0) red[wp] = v;
    __syncthreads();
    if (wp == 0) {
        v = (lane < 8) ? red[lane] : 0.f;
#pragma unroll
        for (int o = 4; o; o >>= 1) v += __shfl_xor_sync(0xffffffffu, v, o);
        if (lane == 0) red[0] = v;
    }
    __syncthreads();
    return red[0];
}

__global__ __launch_bounds__(256) void ln_kernel(
    const float* __restrict__ O, const float* __restrict__ X,
    const float* __restrict__ w, const float* __restrict__ b,
    float* __restrict__ out)
{
    __shared__ float row[HID];
    __shared__ float red[8];
    const int s = blockIdx.x;
    const int tid = threadIdx.x;

    float lsum = 0.f;
    for (int c = tid * 4; c < HID; c += 1024) {
        const float4 o4 = *(const float4*)(O + s * HID + c);
        const float4 x4 = *(const float4*)(X + s * HID + c);
        float4 r;
        r.x = o4.x + x4.x; r.y = o4.y + x4.y;
        r.z = o4.z + x4.z; r.w = o4.w + x4.w;
        *(float4*)&row[c] = r;
        lsum += r.x + r.y + r.z + r.w;
    }
    const float mean = block_sum256(lsum, red) * (1.f / HID);

    float lsq = 0.f;
    for (int c = tid * 4; c < HID; c += 1024) {
        const float4 r = *(const float4*)&row[c];
        const float dx = r.x - mean, dy = r.y - mean;
        const float dz = r.z - mean, dw = r.w - mean;
        lsq += dx * dx + dy * dy + dz * dz + dw * dw;
    }
    const float var  = block_sum256(lsq, red) * (1.f / HID);
    const float rstd = rsqrtf(var + 1e-5f);

    for (int c = tid * 4; c < HID; c += 1024) {
        const float4 r  = *(const float4*)&row[c];
        const float4 w4 = *(const float4*)(w + c);
        const float4 b4 = *(const float4*)(b + c);
        float4 y;
        y.x = (r.x - mean) * rstd * w4.x + b4.x;
        y.y = (r.y - mean) * rstd * w4.y + b4.y;
        y.z = (r.z - mean) * rstd * w4.z + b4.z;
        y.w = (r.w - mean) * rstd * w4.w + b4.w;
        *(float4*)(out + s * HID + c) = y;
    }
}

// ====================================================================
// launch
// ====================================================================
extern "C" void kernel_launch(void* const* d_in, const int* in_sizes, int n_in,
                              void* d_out, int out_size)
{
    const float* x   = (const float*)d_in[0];
    const float* Wq  = (const float*)d_in[1];
    const float* bq  = (const float*)d_in[2];
    const float* Wk  = (const float*)d_in[3];
    const float* bk  = (const float*)d_in[4];
    const float* Wv  = (const float*)d_in[5];
    const float* bv  = (const float*)d_in[6];
    const float* Wo  = (const float*)d_in[7];
    const float* bo  = (const float*)d_in[8];
    const float* lnw = (const float*)d_in[9];
    const float* lnb = (const float*)d_in[10];
    float* out = (float*)d_out;

    float *q, *k, *v, *attn, *o;
    cudaGetSymbolAddress((void**)&q,    g_q);
    cudaGetSymbolAddress((void**)&k,    g_k);
    cudaGetSymbolAddress((void**)&v,    g_v);
    cudaGetSymbolAddress((void**)&attn, g_attn);
    cudaGetSymbolAddress((void**)&o,    g_o);

    const dim3 gemm_grid(HID / 128, SEQ / 128);

    sgemm_nt_bias<<<gemm_grid, 256>>>(x, Wq, bq, q);
    sgemm_nt_bias<<<gemm_grid, 256>>>(x, Wk, bk, k);
    sgemm_nt_bias<<<gemm_grid, 256>>>(x, Wv, bv, v);

    rope_kernel<<<SEQ, 1024>>>(q, k);

    constexpr int FA_SMEM = (3 * 64 * 132 + 64 * 68) * (int)sizeof(float);
    cudaFuncSetAttribute(flash_kernel,
                         cudaFuncAttributeMaxDynamicSharedMemorySize, FA_SMEM);
    flash_kernel<<<dim3(SEQ / 64, NHEADS), 256, FA_SMEM>>>(q, k, v, attn);

    sgemm_nt_bias<<<gemm_grid, 256>>>(attn, Wo, bo, o);

    ln_kernel<<<SEQ, 256>>>(o, x, lnw, lnb, out);
}

// round 4
// speedup vs baseline: 1.5219x; 1.5219x over previous
#include <cuda_runtime.h>
#include <cuda_bf16.h>
#include <math.h>
#include <stdint.h>

#define SEQ    2048
#define HID    2048
#define NHEADS 16
#define DH     128
#define ATT_SCALE 0.08838834764831845f   // 1/sqrt(128)

// ---------------- scratch (device globals: allocation-free) ----------------
__device__ float g_q[SEQ * HID];
__device__ float g_k[SEQ * HID];
__device__ float g_v[SEQ * HID];
__device__ float g_attn[SEQ * HID];
__device__ float g_o[SEQ * HID];
__device__ __nv_bfloat16 g_xhi[SEQ * HID];
__device__ __nv_bfloat16 g_xlo[SEQ * HID];
__device__ __nv_bfloat16 g_whi[3 * HID * HID];
__device__ __nv_bfloat16 g_wlo[3 * HID * HID];

// ====================================================================
// fp32 -> bf16 hi/lo split (3xBF16 scheme)
// ====================================================================
__global__ __launch_bounds__(256) void split_kernel(
    const float* __restrict__ in, __nv_bfloat16* __restrict__ hi,
    __nv_bfloat16* __restrict__ lo, int n4)
{
    const int i = blockIdx.x * 256 + threadIdx.x;
    if (i >= n4) return;
    const float4 v = *(const float4*)(in + i * 4);
    __nv_bfloat16 h0 = __float2bfloat16_rn(v.x);
    __nv_bfloat16 h1 = __float2bfloat16_rn(v.y);
    __nv_bfloat16 h2 = __float2bfloat16_rn(v.z);
    __nv_bfloat16 h3 = __float2bfloat16_rn(v.w);
    __nv_bfloat16 l0 = __float2bfloat16_rn(v.x - __bfloat162float(h0));
    __nv_bfloat16 l1 = __float2bfloat16_rn(v.y - __bfloat162float(h1));
    __nv_bfloat16 l2 = __float2bfloat16_rn(v.z - __bfloat162float(h2));
    __nv_bfloat16 l3 = __float2bfloat16_rn(v.w - __bfloat162float(h3));
    uint2 ph, pl;
    ph.x = (uint32_t)__bfloat16_as_ushort(h0) | ((uint32_t)__bfloat16_as_ushort(h1) << 16);
    ph.y = (uint32_t)__bfloat16_as_ushort(h2) | ((uint32_t)__bfloat16_as_ushort(h3) << 16);
    pl.x = (uint32_t)__bfloat16_as_ushort(l0) | ((uint32_t)__bfloat16_as_ushort(l1) << 16);
    pl.y = (uint32_t)__bfloat16_as_ushort(l2) | ((uint32_t)__bfloat16_as_ushort(l3) << 16);
    *(uint2*)(hi + i * 4) = ph;
    *(uint2*)(lo + i * 4) = pl;
}

// ====================================================================
// bf16 mma.sync GEMM with 3-term split:
// C[M,N] = A@B^T + bias, A/B given as bf16 hi/lo pairs, K-major.
// 128x128 tile, BK=32, 256 threads (warps 4x2), cp.async double buffer.
// smem row pitch = 40 halves (80B) -> conflict-free ldmatrix.
// ====================================================================
#define GBM 128
#define GBN 128
#define GBK 32
#define GKIT (HID / GBK)              // 64
#define PITCH 40                      // halves per smem row
#define TILE_B (128 * PITCH * 2)      // 10240 bytes per tile
#define OFF_AHI 0
#define OFF_ALO (1 * TILE_B)
#define OFF_BHI (2 * TILE_B)
#define OFF_BLO (3 * TILE_B)
#define STAGE_B (4 * TILE_B)          // 40960
#define GEMM_SMEM (2 * STAGE_B)       // 81920

__device__ __forceinline__ uint32_t smem_u32(const void* p) {
    uint32_t a;
    asm("{ .reg .u64 t; cvta.to.shared.u64 t, %1; cvt.u32.u64 %0, t; }"
        : "=r"(a) : "l"(p));
    return a;
}

#define LDSM4(d0, d1, d2, d3, addr)                                        \
    asm volatile("ldmatrix.sync.aligned.m8n8.x4.shared.b16 "               \
                 "{%0,%1,%2,%3}, [%4];"                                    \
                 : "=r"(d0), "=r"(d1), "=r"(d2), "=r"(d3) : "r"(addr))

#define MMA_BF16(acc, a, b)                                                \
    asm volatile("mma.sync.aligned.m16n8k16.row.col.f32.bf16.bf16.f32 "    \
                 "{%0,%1,%2,%3}, {%4,%5,%6,%7}, {%8,%9}, {%0,%1,%2,%3};"   \
                 : "+f"((acc)[0]), "+f"((acc)[1]), "+f"((acc)[2]),         \
                   "+f"((acc)[3])                                          \
                 : "r"((a)[0]), "r"((a)[1]), "r"((a)[2]), "r"((a)[3]),     \
                   "r"((b)[0]), "r"((b)[1]))

#define CPA16(dst, src)                                                    \
    asm volatile("cp.async.cg.shared.global [%0], [%1], 16;"               \
                 :: "r"(dst), "l"(src))

__global__ __launch_bounds__(256, 1) void gemm_bf16s(
    const __nv_bfloat16* __restrict__ Ahi, const __nv_bfloat16* __restrict__ Alo,
    const __nv_bfloat16* __restrict__ Whi, const __nv_bfloat16* __restrict__ Wlo,
    const float* __restrict__ b0, const float* __restrict__ b1,
    const float* __restrict__ b2,
    float* __restrict__ C0, float* __restrict__ C1, float* __restrict__ C2)
{
    extern __shared__ char sm[];
    const uint32_t sbase = smem_u32(sm);

    const int z = blockIdx.z;
    const __nv_bfloat16* Bhi = Whi + (size_t)z * HID * HID;
    const __nv_bfloat16* Blo = Wlo + (size_t)z * HID * HID;
    const float* bias = (z == 0) ? b0 : (z == 1 ? b1 : b2);
    float*       C    = (z == 0) ? C0 : (z == 1 ? C1 : C2);

    const int tid  = threadIdx.x;
    const int lane = tid & 31;
    const int wid  = tid >> 5;
    const int wm   = wid & 3;          // 0..3 : 32-row band
    const int wn   = wid >> 2;         // 0..1 : 64-col band
    const int bm = blockIdx.y * GBM;
    const int bn = blockIdx.x * GBN;

    // loader mapping: row = tid>>1 (0..127), halves col = (tid&1)*16 (+0,+8)
    const int lrow = tid >> 1;
    const int lcol = (tid & 1) * 16;
    const uint32_t sdst = (uint32_t)(lrow * (PITCH * 2) + lcol * 2); // bytes
    const __nv_bfloat16* pAhi = Ahi + (size_t)(bm + lrow) * HID + lcol;
    const __nv_bfloat16* pAlo = Alo + (size_t)(bm + lrow) * HID + lcol;
    const __nv_bfloat16* pBhi = Bhi + (size_t)(bn + lrow) * HID + lcol;
    const __nv_bfloat16* pBlo = Blo + (size_t)(bn + lrow) * HID + lcol;

    float acc[2][8][4];
#pragma unroll
    for (int mi = 0; mi < 2; ++mi)
#pragma unroll
        for (int nj = 0; nj < 8; ++nj)
#pragma unroll
            for (int c = 0; c < 4; ++c) acc[mi][nj][c] = 0.f;

    auto load_stage = [&](int kt, int buf) {
        const int k0 = kt * GBK;
        const uint32_t s = sbase + buf * STAGE_B + sdst;
        CPA16(s + OFF_AHI,      pAhi + k0);
        CPA16(s + OFF_AHI + 16, pAhi + k0 + 8);
        CPA16(s + OFF_ALO,      pAlo + k0);
        CPA16(s + OFF_ALO + 16, pAlo + k0 + 8);
        CPA16(s + OFF_BHI,      pBhi + k0);
        CPA16(s + OFF_BHI + 16, pBhi + k0 + 8);
        CPA16(s + OFF_BLO,      pBlo + k0);
        CPA16(s + OFF_BLO + 16, pBlo + k0 + 8);
    };

    load_stage(0, 0);
    asm volatile("cp.async.commit_group;");

    int buf = 0;
    for (int kt = 0; kt < GKIT; ++kt) {
        if (kt + 1 < GKIT) load_stage(kt + 1, buf ^ 1);
        asm volatile("cp.async.commit_group;");
        asm volatile("cp.async.wait_group 1;");
        __syncthreads();

        const uint32_t sA_hi = sbase + buf * STAGE_B + OFF_AHI;
        const uint32_t sA_lo = sbase + buf * STAGE_B + OFF_ALO;
        const uint32_t sB_hi = sbase + buf * STAGE_B + OFF_BHI;
        const uint32_t sB_lo = sbase + buf * STAGE_B + OFF_BLO;

#pragma unroll
        for (int kk = 0; kk < 2; ++kk) {          // two k16 halves of BK=32
            uint32_t a_hi[2][4], a_lo[2][4], b_hi[8][2], b_lo[8][2];
            const int r16 = lane & 15;
            const int ksel = lane >> 4;           // 0/1
#pragma unroll
            for (int mi = 0; mi < 2; ++mi) {
                const uint32_t off =
                    (uint32_t)((wm * 32 + mi * 16 + r16) * (PITCH * 2) +
                               (kk * 2 + ksel) * 16);
                LDSM4(a_hi[mi][0], a_hi[mi][1], a_hi[mi][2], a_hi[mi][3],
                      sA_hi + off);
                LDSM4(a_lo[mi][0], a_lo[mi][1], a_lo[mi][2], a_lo[mi][3],
                      sA_lo + off);
            }
            const int q  = lane >> 3;             // 0..3
            const int rr = lane & 7;
#pragma unroll
            for (int a2 = 0; a2 < 4; ++a2) {      // pairs of n8 groups
                const int row = wn * 64 + a2 * 16 + (q >> 1) * 8 + rr;
                const uint32_t off =
                    (uint32_t)(row * (PITCH * 2) + (kk * 2 + (q & 1)) * 16);
                LDSM4(b_hi[a2 * 2][0], b_hi[a2 * 2][1],
                      b_hi[a2 * 2 + 1][0], b_hi[a2 * 2 + 1][1], sB_hi + off);
                LDSM4(b_lo[a2 * 2][0], b_lo[a2 * 2][1],
                      b_lo[a2 * 2 + 1][0], b_lo[a2 * 2 + 1][1], sB_lo + off);
            }
#pragma unroll
            for (int mi = 0; mi < 2; ++mi)
#pragma unroll
                for (int nj = 0; nj < 8; ++nj) {
                    MMA_BF16(acc[mi][nj], a_hi[mi], b_hi[nj]);
                    MMA_BF16(acc[mi][nj], a_hi[mi], b_lo[nj]);
                    MMA_BF16(acc[mi][nj], a_lo[mi], b_hi[nj]);
                }
        }
        __syncthreads();
        buf ^= 1;
    }

    // epilogue: c0,c1 -> (row, col..col+1), c2,c3 -> (row+8, col..col+1)
    const int trow = lane >> 2;
    const int tcol = (lane & 3) * 2;
#pragma unroll
    for (int mi = 0; mi < 2; ++mi) {
        const int r = bm + wm * 32 + mi * 16 + trow;
#pragma unroll
        for (int nj = 0; nj < 8; ++nj) {
            const int c = bn + wn * 64 + nj * 8 + tcol;
            const float bx = bias[c], by = bias[c + 1];
            float2 o;
            o.x = acc[mi][nj][0] + bx; o.y = acc[mi][nj][1] + by;
            *(float2*)(C + (size_t)r * HID + c) = o;
            o.x = acc[mi][nj][2] + bx; o.y = acc[mi][nj][3] + by;
            *(float2*)(C + (size_t)(r + 8) * HID + c) = o;
        }
    }
}

// ====================================================================
// RoPE on q and k in place (matches reference fp32 angle rounding).
// ====================================================================
__global__ __launch_bounds__(1024) void rope_kernel(float* __restrict__ q,
                                                    float* __restrict__ k)
{
    const int s = blockIdx.x;
    const int t = threadIdx.x;
    const int h = t >> 6;
    const int i = t & 63;

    const float invf = (float)pow(10000.0, -(double)(2 * i) / 128.0);
    const float ang  = (float)s * invf;
    const float c  = (float)cos((double)ang);
    const float sn = (float)sin((double)ang);

    const int base = s * HID + h * DH + i;
    float a = q[base], b = q[base + 64];
    q[base]      = a * c - b * sn;
    q[base + 64] = b * c + a * sn;
    a = k[base];  b = k[base + 64];
    k[base]      = a * c - b * sn;
    k[base + 64] = b * c + a * sn;
}

// ====================================================================
// Flash attention (fp32, causal), unchanged from passing baseline.
// ====================================================================
__global__ __launch_bounds__(256) void flash_kernel(
    const float* __restrict__ Qg, const float* __restrict__ Kg,
    const float* __restrict__ Vg, float* __restrict__ Og)
{
    extern __shared__ float smf[];
    float* sQ = smf;
    float* sK = sQ + 64 * 132;
    float* sV = sK + 64 * 132;
    float* sP = sV + 64 * 132;

    const int h  = blockIdx.y;
    const int q0 = blockIdx.x * 64;
    const int tid = threadIdx.x;
    const int tr = tid >> 4;
    const int tc = tid & 15;

    for (int idx = tid; idx < 64 * 32; idx += 256) {
        const int r = idx >> 5;
        const int c = (idx & 31) << 2;
        *(float4*)&sQ[r * 132 + c] =
            *(const float4*)(Qg + (q0 + r) * HID + h * DH + c);
    }

    float m_i[4], l_i[4], oacc[4][8];
#pragma unroll
    for (int i = 0; i < 4; i++) {
        m_i[i] = -1e30f; l_i[i] = 0.f;
#pragma unroll
        for (int c = 0; c < 8; c++) oacc[i][c] = 0.f;
    }
    __syncthreads();

    const int ntiles = (q0 >> 6) + 1;
    for (int t = 0; t < ntiles; t++) {
        const int j0 = t << 6;
        for (int idx = tid; idx < 64 * 32; idx += 256) {
            const int r = idx >> 5;
            const int c = (idx & 31) << 2;
            *(float4*)&sK[r * 132 + c] =
                *(const float4*)(Kg + (j0 + r) * HID + h * DH + c);
            *(float4*)&sV[r * 132 + c] =
                *(const float4*)(Vg + (j0 + r) * HID + h * DH + c);
        }
        __syncthreads();

        float sc[4][4];
#pragma unroll
        for (int i = 0; i < 4; i++)
#pragma unroll
            for (int j = 0; j < 4; j++) sc[i][j] = 0.f;

        for (int d = 0; d < DH; d += 4) {
            float4 qv[4], kv[4];
#pragma unroll
            for (int i = 0; i < 4; i++)
                qv[i] = *(const float4*)&sQ[(tr * 4 + i) * 132 + d];
#pragma unroll
            for (int j = 0; j < 4; j++)
                kv[j] = *(const float4*)&sK[(tc * 4 + j) * 132 + d];
#pragma unroll
            for (int i = 0; i < 4; i++)
#pragma unroll
                for (int j = 0; j < 4; j++) {
                    sc[i][j] = fmaf(qv[i].x, kv[j].x, sc[i][j]);
                    sc[i][j] = fmaf(qv[i].y, kv[j].y, sc[i][j]);
                    sc[i][j] = fmaf(qv[i].z, kv[j].z, sc[i][j]);
                    sc[i][j] = fmaf(qv[i].w, kv[j].w, sc[i][j]);
                }
        }

        const bool diag = (j0 == q0);
#pragma unroll
        for (int i = 0; i < 4; i++) {
            const int gr = tr * 4 + i;
#pragma unroll
            for (int j = 0; j < 4; j++) {
                sc[i][j] *= ATT_SCALE;
                if (diag && (tc * 4 + j > gr)) sc[i][j] = -1e30f;
            }
        }

#pragma unroll
        for (int i = 0; i < 4; i++) {
            float mx = fmaxf(fmaxf(sc[i][0], sc[i][1]), fmaxf(sc[i][2], sc[i][3]));
#pragma unroll
            for (int off = 8; off >= 1; off >>= 1)
                mx = fmaxf(mx, __shfl_xor_sync(0xffffffffu, mx, off));
            const float mnew  = fmaxf(m_i[i], mx);
            const float alpha = __expf(m_i[i] - mnew);
            float rs = 0.f;
#pragma unroll
            for (int j = 0; j < 4; j++) {
                sc[i][j] = __expf(sc[i][j] - mnew);
                rs += sc[i][j];
            }
#pragma unroll
            for (int off = 8; off >= 1; off >>= 1)
                rs += __shfl_xor_sync(0xffffffffu, rs, off);
            l_i[i] = l_i[i] * alpha + rs;
            m_i[i] = mnew;
#pragma unroll
            for (int c = 0; c < 8; c++) oacc[i][c] *= alpha;
            float* pp = &sP[(tr * 4 + i) * 68 + tc * 4];
            pp[0] = sc[i][0]; pp[1] = sc[i][1];
            pp[2] = sc[i][2]; pp[3] = sc[i][3];
        }
        __syncthreads();

        for (int j = 0; j < 64; j++) {
            const float4 v0 = *(const float4*)&sV[j * 132 + tc * 8];
            const float4 v1 = *(const float4*)&sV[j * 132 + tc * 8 + 4];
#pragma unroll
            for (int i = 0; i < 4; i++) {
                const float p = sP[(tr * 4 + i) * 68 + j];
                oacc[i][0] = fmaf(p, v0.x, oacc[i][0]);
                oacc[i][1] = fmaf(p, v0.y, oacc[i][1]);
                oacc[i][2] = fmaf(p, v0.z, oacc[i][2]);
                oacc[i][3] = fmaf(p, v0.w, oacc[i][3]);
                oacc[i][4] = fmaf(p, v1.x, oacc[i][4]);
                oacc[i][5] = fmaf(p, v1.y, oacc[i][5]);
                oacc[i][6] = fmaf(p, v1.z, oacc[i][6]);
                oacc[i][7] = fmaf(p, v1.w, oacc[i][7]);
            }
        }
        __syncthreads();
    }

#pragma unroll
    for (int i = 0; i < 4; i++) {
        const float inv = 1.f / l_i[i];
        float4 o0, o1;
        o0.x = oacc[i][0] * inv; o0.y = oacc[i][1] * inv;
        o0.z = oacc[i][2] * inv; o0.w = oacc[i][3] * inv;
        o1.x = oacc[i][4] * inv; o1.y = oacc[i][5] * inv;
        o1.z = oacc[i][6] * inv; o1.w = oacc[i][7] * inv;
        float* Op = Og + (q0 + tr * 4 + i) * HID + h * DH + tc * 8;
        *(float4*)Op = o0;
        *(float4*)(Op + 4) = o1;
    }
}

// ====================================================================
// Residual + LayerNorm.
// ====================================================================
__device__ __forceinline__ float block_sum256(float v, float* red)
{
    __syncthreads();
    const int lane = threadIdx.x & 31;
    const int wp   = threadIdx.x >> 5;
#pragma unroll
    for (int o = 16; o; o >>= 1) v += __shfl_xor_sync(0xffffffffu, v, o);
    if (lane == 0) red[wp] = v;
    __syncthreads();
    if (wp == 0) {
        v = (lane < 8) ? red[lane] : 0.f;
#pragma unroll
        for (int o = 4; o; o >>= 1) v += __shfl_xor_sync(0xffffffffu, v, o);
        if (lane == 0) red[0] = v;
    }
    __syncthreads();
    return red[0];
}

__global__ __launch_bounds__(256) void ln_kernel(
    const float* __restrict__ O, const float* __restrict__ X,
    const float* __restrict__ w, const float* __restrict__ b,
    float* __restrict__ out)
{
    __shared__ float row[HID];
    __shared__ float red[8];
    const int s = blockIdx.x;
    const int tid = threadIdx.x;

    float lsum = 0.f;
    for (int c = tid * 4; c < HID; c += 1024) {
        const float4 o4 = *(const float4*)(O + s * HID + c);
        const float4 x4 = *(const float4*)(X + s * HID + c);
        float4 r;
        r.x = o4.x + x4.x; r.y = o4.y + x4.y;
        r.z = o4.z + x4.z; r.w = o4.w + x4.w;
        *(float4*)&row[c] = r;
        lsum += r.x + r.y + r.z + r.w;
    }
    const float mean = block_sum256(lsum, red) * (1.f / HID);

    float lsq = 0.f;
    for (int c = tid * 4; c < HID; c += 1024) {
        const float4 r = *(const float4*)&row[c];
        const float dx = r.x - mean, dy = r.y - mean;
        const float dz = r.z - mean, dw = r.w - mean;
        lsq += dx * dx + dy * dy + dz * dz + dw * dw;
    }
    const float var  = block_sum256(lsq, red) * (1.f / HID);
    const float rstd = rsqrtf(var + 1e-5f);

    for (int c = tid * 4; c < HID; c += 1024) {
        const float4 r  = *(const float4*)&row[c];
        const float4 w4 = *(const float4*)(w + c);
        const float4 b4 = *(const float4*)(b + c);
        float4 y;
        y.x = (r.x - mean) * rstd * w4.x + b4.x;
        y.y = (r.y - mean) * rstd * w4.y + b4.y;
        y.z = (r.z - mean) * rstd * w4.z + b4.z;
        y.w = (r.w - mean) * rstd * w4.w + b4.w;
        *(float4*)(out + s * HID + c) = y;
    }
}

// ====================================================================
// launch
// ====================================================================
extern "C" void kernel_launch(void* const* d_in, const int* in_sizes, int n_in,
                              void* d_out, int out_size)
{
    const float* x   = (const float*)d_in[0];
    const float* Wq  = (const float*)d_in[1];
    const float* bq  = (const float*)d_in[2];
    const float* Wk  = (const float*)d_in[3];
    const float* bk  = (const float*)d_in[4];
    const float* Wv  = (const float*)d_in[5];
    const float* bv  = (const float*)d_in[6];
    const float* Wo  = (const float*)d_in[7];
    const float* bo  = (const float*)d_in[8];
    const float* lnw = (const float*)d_in[9];
    const float* lnb = (const float*)d_in[10];
    float* out = (float*)d_out;

    float *q, *k, *v, *attn, *o;
    __nv_bfloat16 *xhi, *xlo, *whi, *wlo;
    cudaGetSymbolAddress((void**)&q,    g_q);
    cudaGetSymbolAddress((void**)&k,    g_k);
    cudaGetSymbolAddress((void**)&v,    g_v);
    cudaGetSymbolAddress((void**)&attn, g_attn);
    cudaGetSymbolAddress((void**)&o,    g_o);
    cudaGetSymbolAddress((void**)&xhi,  g_xhi);
    cudaGetSymbolAddress((void**)&xlo,  g_xlo);
    cudaGetSymbolAddress((void**)&whi,  g_whi);
    cudaGetSymbolAddress((void**)&wlo,  g_wlo);

    cudaFuncSetAttribute(gemm_bf16s,
                         cudaFuncAttributeMaxDynamicSharedMemorySize, GEMM_SMEM);

    const int N4  = SEQ * HID / 4;        // elements/4 for one matrix
    const int SGR = N4 / 256;             // split grid

    // ---- QKV phase ----
    split_kernel<<<SGR, 256>>>(x,  xhi, xlo, N4);
    split_kernel<<<SGR, 256>>>(Wq, whi,                wlo,                N4);
    split_kernel<<<SGR, 256>>>(Wk, whi + HID * HID,    wlo + HID * HID,    N4);
    split_kernel<<<SGR, 256>>>(Wv, whi + 2 * HID * HID, wlo + 2 * HID * HID, N4);

    gemm_bf16s<<<dim3(HID / GBN, SEQ / GBM, 3), 256, GEMM_SMEM>>>(
        xhi, xlo, whi, wlo, bq, bk, bv, q, k, v);

    rope_kernel<<<SEQ, 1024>>>(q, k);

    constexpr int FA_SMEM = (3 * 64 * 132 + 64 * 68) * (int)sizeof(float);
    cudaFuncSetAttribute(flash_kernel,
                         cudaFuncAttributeMaxDynamicSharedMemorySize, FA_SMEM);
    flash_kernel<<<dim3(SEQ / 64, NHEADS), 256, FA_SMEM>>>(q, k, v, attn);

    // ---- O projection ----
    split_kernel<<<SGR, 256>>>(attn, xhi, xlo, N4);
    split_kernel<<<SGR, 256>>>(Wo,   whi, wlo, N4);

    gemm_bf16s<<<dim3(HID / GBN, SEQ / GBM, 1), 256, GEMM_SMEM>>>(
        xhi, xlo, whi, wlo, bo, bo, bo, o, o, o);

    ln_kernel<<<SEQ, 256>>>(o, x, lnw, lnb, out);
}

// round 5
// speedup vs baseline: 2.8530x; 1.8746x over previous
#include <cuda_runtime.h>
#include <cuda_bf16.h>
#include <math.h>
#include <stdint.h>

#define SEQ    2048
#define HID    2048
#define NHEADS 16
#define DH     128
#define ATT_SCALE 0.08838834764831845f   // 1/sqrt(128)

// ---------------- scratch (device globals: allocation-free) ----------------
__device__ float g_q[SEQ * HID];
__device__ float g_k[SEQ * HID];
__device__ float g_v[SEQ * HID];
__device__ float g_attn[SEQ * HID];
__device__ float g_o[SEQ * HID];
__device__ __nv_bfloat16 g_xhi[SEQ * HID];
__device__ __nv_bfloat16 g_xlo[SEQ * HID];
__device__ __nv_bfloat16 g_whi[3 * HID * HID];
__device__ __nv_bfloat16 g_wlo[3 * HID * HID];
__device__ __nv_bfloat16 g_qhi[SEQ * HID];
__device__ __nv_bfloat16 g_qlo[SEQ * HID];
__device__ __nv_bfloat16 g_khi[SEQ * HID];
__device__ __nv_bfloat16 g_klo[SEQ * HID];
__device__ __nv_bfloat16 g_vhi[SEQ * HID];
__device__ __nv_bfloat16 g_vlo[SEQ * HID];

// ====================================================================
// common helpers
// ====================================================================
__device__ __forceinline__ uint32_t smem_u32(const void* p) {
    uint32_t a;
    asm("{ .reg .u64 t; cvta.to.shared.u64 t, %1; cvt.u32.u64 %0, t; }"
        : "=r"(a) : "l"(p));
    return a;
}

__device__ __forceinline__ void bsplit(float x, __nv_bfloat16& h, __nv_bfloat16& l) {
    h = __float2bfloat16_rn(x);
    l = __float2bfloat16_rn(x - __bfloat162float(h));
}

#define LDSM4(d0, d1, d2, d3, addr)                                        \
    asm volatile("ldmatrix.sync.aligned.m8n8.x4.shared.b16 "               \
                 "{%0,%1,%2,%3}, [%4];"                                    \
                 : "=r"(d0), "=r"(d1), "=r"(d2), "=r"(d3) : "r"(addr))

#define LDSM4T(d0, d1, d2, d3, addr)                                       \
    asm volatile("ldmatrix.sync.aligned.m8n8.x4.trans.shared.b16 "         \
                 "{%0,%1,%2,%3}, [%4];"                                    \
                 : "=r"(d0), "=r"(d1), "=r"(d2), "=r"(d3) : "r"(addr))

#define MMA_BF16(acc, a, b)                                                \
    asm volatile("mma.sync.aligned.m16n8k16.row.col.f32.bf16.bf16.f32 "    \
                 "{%0,%1,%2,%3}, {%4,%5,%6,%7}, {%8,%9}, {%0,%1,%2,%3};"   \
                 : "+f"((acc)[0]), "+f"((acc)[1]), "+f"((acc)[2]),         \
                   "+f"((acc)[3])                                          \
                 : "r"((a)[0]), "r"((a)[1]), "r"((a)[2]), "r"((a)[3]),     \
                   "r"((b)[0]), "r"((b)[1]))

#define CPA16(dst, src)                                                    \
    asm volatile("cp.async.cg.shared.global [%0], [%1], 16;"               \
                 :: "r"(dst), "l"(src))

// ====================================================================
// fp32 -> bf16 hi/lo split
// ====================================================================
__global__ __launch_bounds__(256) void split_kernel(
    const float* __restrict__ in, __nv_bfloat16* __restrict__ hi,
    __nv_bfloat16* __restrict__ lo, int n4)
{
    const int i = blockIdx.x * 256 + threadIdx.x;
    if (i >= n4) return;
    const float4 v = *(const float4*)(in + i * 4);
    __nv_bfloat16 h0, h1, h2, h3, l0, l1, l2, l3;
    bsplit(v.x, h0, l0); bsplit(v.y, h1, l1);
    bsplit(v.z, h2, l2); bsplit(v.w, h3, l3);
    uint2 ph, pl;
    ph.x = (uint32_t)__bfloat16_as_ushort(h0) | ((uint32_t)__bfloat16_as_ushort(h1) << 16);
    ph.y = (uint32_t)__bfloat16_as_ushort(h2) | ((uint32_t)__bfloat16_as_ushort(h3) << 16);
    pl.x = (uint32_t)__bfloat16_as_ushort(l0) | ((uint32_t)__bfloat16_as_ushort(l1) << 16);
    pl.y = (uint32_t)__bfloat16_as_ushort(l2) | ((uint32_t)__bfloat16_as_ushort(l3) << 16);
    *(uint2*)(hi + i * 4) = ph;
    *(uint2*)(lo + i * 4) = pl;
}

// ====================================================================
// RoPE + bf16 split for q,k (reads fp32 GEMM outputs, writes hi/lo)
// ====================================================================
__global__ __launch_bounds__(1024) void rope_split_kernel(
    const float* __restrict__ q, const float* __restrict__ k,
    __nv_bfloat16* __restrict__ qhi, __nv_bfloat16* __restrict__ qlo,
    __nv_bfloat16* __restrict__ khi, __nv_bfloat16* __restrict__ klo)
{
    const int s = blockIdx.x;
    const int t = threadIdx.x;
    const int h = t >> 6;
    const int i = t & 63;

    const float invf = (float)pow(10000.0, -(double)(2 * i) / 128.0);
    const float ang  = (float)s * invf;
    const float c  = (float)cos((double)ang);
    const float sn = (float)sin((double)ang);

    const int base = s * HID + h * DH + i;
    __nv_bfloat16 hh, ll;

    float a = q[base], b = q[base + 64];
    float x0 = a * c - b * sn, x1 = b * c + a * sn;
    bsplit(x0, hh, ll); qhi[base]      = hh; qlo[base]      = ll;
    bsplit(x1, hh, ll); qhi[base + 64] = hh; qlo[base + 64] = ll;

    a = k[base];  b = k[base + 64];
    x0 = a * c - b * sn; x1 = b * c + a * sn;
    bsplit(x0, hh, ll); khi[base]      = hh; klo[base]      = ll;
    bsplit(x1, hh, ll); khi[base + 64] = hh; klo[base + 64] = ll;
}

// ====================================================================
// bf16 mma.sync GEMM with 3-term split (unchanged from R4 pass)
// ====================================================================
#define GBM 128
#define GBN 128
#define GBK 32
#define GKIT (HID / GBK)
#define PITCH 40
#define TILE_B (128 * PITCH * 2)
#define OFF_AHI 0
#define OFF_ALO (1 * TILE_B)
#define OFF_BHI (2 * TILE_B)
#define OFF_BLO (3 * TILE_B)
#define STAGE_B (4 * TILE_B)
#define GEMM_SMEM (2 * STAGE_B)

__global__ __launch_bounds__(256, 1) void gemm_bf16s(
    const __nv_bfloat16* __restrict__ Ahi, const __nv_bfloat16* __restrict__ Alo,
    const __nv_bfloat16* __restrict__ Whi, const __nv_bfloat16* __restrict__ Wlo,
    const float* __restrict__ b0, const float* __restrict__ b1,
    const float* __restrict__ b2,
    float* __restrict__ C0, float* __restrict__ C1, float* __restrict__ C2)
{
    extern __shared__ char sm[];
    const uint32_t sbase = smem_u32(sm);

    const int z = blockIdx.z;
    const __nv_bfloat16* Bhi = Whi + (size_t)z * HID * HID;
    const __nv_bfloat16* Blo = Wlo + (size_t)z * HID * HID;
    const float* bias = (z == 0) ? b0 : (z == 1 ? b1 : b2);
    float*       C    = (z == 0) ? C0 : (z == 1 ? C1 : C2);

    const int tid  = threadIdx.x;
    const int lane = tid & 31;
    const int wid  = tid >> 5;
    const int wm   = wid & 3;
    const int wn   = wid >> 2;
    const int bm = blockIdx.y * GBM;
    const int bn = blockIdx.x * GBN;

    const int lrow = tid >> 1;
    const int lcol = (tid & 1) * 16;
    const uint32_t sdst = (uint32_t)(lrow * (PITCH * 2) + lcol * 2);
    const __nv_bfloat16* pAhi = Ahi + (size_t)(bm + lrow) * HID + lcol;
    const __nv_bfloat16* pAlo = Alo + (size_t)(bm + lrow) * HID + lcol;
    const __nv_bfloat16* pBhi = Bhi + (size_t)(bn + lrow) * HID + lcol;
    const __nv_bfloat16* pBlo = Blo + (size_t)(bn + lrow) * HID + lcol;

    float acc[2][8][4];
#pragma unroll
    for (int mi = 0; mi < 2; ++mi)
#pragma unroll
        for (int nj = 0; nj < 8; ++nj)
#pragma unroll
            for (int c = 0; c < 4; ++c) acc[mi][nj][c] = 0.f;

    auto load_stage = [&](int kt, int buf) {
        const int k0 = kt * GBK;
        const uint32_t s = sbase + buf * STAGE_B + sdst;
        CPA16(s + OFF_AHI,      pAhi + k0);
        CPA16(s + OFF_AHI + 16, pAhi + k0 + 8);
        CPA16(s + OFF_ALO,      pAlo + k0);
        CPA16(s + OFF_ALO + 16, pAlo + k0 + 8);
        CPA16(s + OFF_BHI,      pBhi + k0);
        CPA16(s + OFF_BHI + 16, pBhi + k0 + 8);
        CPA16(s + OFF_BLO,      pBlo + k0);
        CPA16(s + OFF_BLO + 16, pBlo + k0 + 8);
    };

    load_stage(0, 0);
    asm volatile("cp.async.commit_group;");

    int buf = 0;
    for (int kt = 0; kt < GKIT; ++kt) {
        if (kt + 1 < GKIT) load_stage(kt + 1, buf ^ 1);
        asm volatile("cp.async.commit_group;");
        asm volatile("cp.async.wait_group 1;");
        __syncthreads();

        const uint32_t sA_hi = sbase + buf * STAGE_B + OFF_AHI;
        const uint32_t sA_lo = sbase + buf * STAGE_B + OFF_ALO;
        const uint32_t sB_hi = sbase + buf * STAGE_B + OFF_BHI;
        const uint32_t sB_lo = sbase + buf * STAGE_B + OFF_BLO;

#pragma unroll
        for (int kk = 0; kk < 2; ++kk) {
            uint32_t a_hi[2][4], a_lo[2][4], b_hi[8][2], b_lo[8][2];
            const int r16 = lane & 15;
            const int ksel = lane >> 4;
#pragma unroll
            for (int mi = 0; mi < 2; ++mi) {
                const uint32_t off =
                    (uint32_t)((wm * 32 + mi * 16 + r16) * (PITCH * 2) +
                               (kk * 2 + ksel) * 16);
                LDSM4(a_hi[mi][0], a_hi[mi][1], a_hi[mi][2], a_hi[mi][3],
                      sA_hi + off);
                LDSM4(a_lo[mi][0], a_lo[mi][1], a_lo[mi][2], a_lo[mi][3],
                      sA_lo + off);
            }
            const int q  = lane >> 3;
            const int rr = lane & 7;
#pragma unroll
            for (int a2 = 0; a2 < 4; ++a2) {
                const int row = wn * 64 + a2 * 16 + (q >> 1) * 8 + rr;
                const uint32_t off =
                    (uint32_t)(row * (PITCH * 2) + (kk * 2 + (q & 1)) * 16);
                LDSM4(b_hi[a2 * 2][0], b_hi[a2 * 2][1],
                      b_hi[a2 * 2 + 1][0], b_hi[a2 * 2 + 1][1], sB_hi + off);
                LDSM4(b_lo[a2 * 2][0], b_lo[a2 * 2][1],
                      b_lo[a2 * 2 + 1][0], b_lo[a2 * 2 + 1][1], sB_lo + off);
            }
#pragma unroll
            for (int mi = 0; mi < 2; ++mi)
#pragma unroll
                for (int nj = 0; nj < 8; ++nj) {
                    MMA_BF16(acc[mi][nj], a_hi[mi], b_hi[nj]);
                    MMA_BF16(acc[mi][nj], a_hi[mi], b_lo[nj]);
                    MMA_BF16(acc[mi][nj], a_lo[mi], b_hi[nj]);
                }
        }
        __syncthreads();
        buf ^= 1;
    }

    const int trow = lane >> 2;
    const int tcol = (lane & 3) * 2;
#pragma unroll
    for (int mi = 0; mi < 2; ++mi) {
        const int r = bm + wm * 32 + mi * 16 + trow;
#pragma unroll
        for (int nj = 0; nj < 8; ++nj) {
            const int c = bn + wn * 64 + nj * 8 + tcol;
            const float bx = bias[c], by = bias[c + 1];
            float2 o;
            o.x = acc[mi][nj][0] + bx; o.y = acc[mi][nj][1] + by;
            *(float2*)(C + (size_t)r * HID + c) = o;
            o.x = acc[mi][nj][2] + bx; o.y = acc[mi][nj][3] + by;
            *(float2*)(C + (size_t)(r + 8) * HID + c) = o;
        }
    }
}

// ====================================================================
// Flash attention on bf16 mma.sync (3xBF16 split for QK and PV).
// CTA = 128 q-rows x 1 head; 8 warps, each owns m16.
// ====================================================================
#define FP_B 272                   // smem row pitch bytes (136 halves)
#define QTILE_FB (128 * FP_B)      // 34816
#define KVTILE_FB (64 * FP_B)      // 17408
#define FKV0 (2 * QTILE_FB)        // 69632
#define FKSTG (4 * KVTILE_FB)      // 69632
#define FLASH_SMEM (FKV0 + 2 * FKSTG)   // 208896

__global__ __launch_bounds__(256, 1) void flash_tc(
    const __nv_bfloat16* __restrict__ qhi, const __nv_bfloat16* __restrict__ qlo,
    const __nv_bfloat16* __restrict__ khi, const __nv_bfloat16* __restrict__ klo,
    const __nv_bfloat16* __restrict__ vhi, const __nv_bfloat16* __restrict__ vlo,
    float* __restrict__ Og)
{
    extern __shared__ char sm[];
    const uint32_t sb = smem_u32(sm);
    const int h  = blockIdx.y;
    const int qb = blockIdx.x;
    const int q0 = qb * 128;
    const int tid = threadIdx.x, lane = tid & 31, wm = tid >> 5;

    // Q tiles (hi/lo), loaded once
    {
        const __nv_bfloat16* ph = qhi + (size_t)q0 * HID + h * DH;
        const __nv_bfloat16* pl = qlo + (size_t)q0 * HID + h * DH;
#pragma unroll
        for (int i = 0; i < 8; ++i) {
            const int idx = tid + i * 256, row = idx >> 4, c = idx & 15;
            const uint32_t d = (uint32_t)(row * FP_B + c * 16);
            CPA16(sb + d,            ph + (size_t)row * HID + c * 8);
            CPA16(sb + QTILE_FB + d, pl + (size_t)row * HID + c * 8);
        }
    }

    auto load_kv = [&](int t, int b) {
        const int j0 = t * 64;
        const uint32_t s = sb + FKV0 + b * FKSTG;
#pragma unroll
        for (int i = 0; i < 4; ++i) {
            const int idx = tid + i * 256, row = idx >> 4, c = idx & 15;
            const uint32_t d = (uint32_t)(row * FP_B + c * 16);
            const size_t g = (size_t)(j0 + row) * HID + h * DH + c * 8;
            CPA16(s + 0 * KVTILE_FB + d, khi + g);
            CPA16(s + 1 * KVTILE_FB + d, klo + g);
            CPA16(s + 2 * KVTILE_FB + d, vhi + g);
            CPA16(s + 3 * KVTILE_FB + d, vlo + g);
        }
    };

    load_kv(0, 0);
    asm volatile("cp.async.commit_group;");

    float o[16][4];
#pragma unroll
    for (int f = 0; f < 16; ++f)
#pragma unroll
        for (int c = 0; c < 4; ++c) o[f][c] = 0.f;
    float m0 = -1e30f, m1 = -1e30f, l0 = 0.f, l1 = 0.f;

    const int ntiles = 2 * qb + 2;
    int buf = 0;
    for (int t = 0; t < ntiles; ++t) {
        if (t + 1 < ntiles) load_kv(t + 1, buf ^ 1);
        asm volatile("cp.async.commit_group;");
        asm volatile("cp.async.wait_group 1;");
        __syncthreads();

        const int j0 = t * 64;
        const uint32_t skh = sb + FKV0 + buf * FKSTG;
        const uint32_t skl = skh + KVTILE_FB;
        const uint32_t svh = skh + 2 * KVTILE_FB;
        const uint32_t svl = skh + 3 * KVTILE_FB;

        if (j0 <= q0 + wm * 16 + 15) {
            // ---- S = Q K^T (3-term split) ----
            float sc[8][4];
#pragma unroll
            for (int nj = 0; nj < 8; ++nj)
#pragma unroll
                for (int c = 0; c < 4; ++c) sc[nj][c] = 0.f;

            const int r16 = lane & 15, ksel = lane >> 4;
            const int qq = lane >> 3, rr = lane & 7;
#pragma unroll
            for (int kk = 0; kk < 8; ++kk) {
                uint32_t ah[4], al[4];
                const uint32_t aoff =
                    (uint32_t)((wm * 16 + r16) * FP_B + (kk * 2 + ksel) * 16);
                LDSM4(ah[0], ah[1], ah[2], ah[3], sb + aoff);
                LDSM4(al[0], al[1], al[2], al[3], sb + QTILE_FB + aoff);
                uint32_t bh[8][2], bl[8][2];
#pragma unroll
                for (int a2 = 0; a2 < 4; ++a2) {
                    const uint32_t boff =
                        (uint32_t)((a2 * 16 + (qq >> 1) * 8 + rr) * FP_B +
                                   (kk * 2 + (qq & 1)) * 16);
                    LDSM4(bh[a2 * 2][0], bh[a2 * 2][1],
                          bh[a2 * 2 + 1][0], bh[a2 * 2 + 1][1], skh + boff);
                    LDSM4(bl[a2 * 2][0], bl[a2 * 2][1],
                          bl[a2 * 2 + 1][0], bl[a2 * 2 + 1][1], skl + boff);
                }
#pragma unroll
                for (int nj = 0; nj < 8; ++nj) {
                    MMA_BF16(sc[nj], ah, bh[nj]);
                    MMA_BF16(sc[nj], ah, bl[nj]);
                    MMA_BF16(sc[nj], al, bh[nj]);
                }
            }

            // ---- scale + causal mask ----
            const int r0g = q0 + wm * 16 + (lane >> 2);
            const bool needMask = (j0 + 63 > q0 + wm * 16);
#pragma unroll
            for (int nj = 0; nj < 8; ++nj) {
                const int c0 = j0 + nj * 8 + (lane & 3) * 2;
                sc[nj][0] *= ATT_SCALE; sc[nj][1] *= ATT_SCALE;
                sc[nj][2] *= ATT_SCALE; sc[nj][3] *= ATT_SCALE;
                if (needMask) {
                    if (c0     > r0g)     sc[nj][0] = -1e30f;
                    if (c0 + 1 > r0g)     sc[nj][1] = -1e30f;
                    if (c0     > r0g + 8) sc[nj][2] = -1e30f;
                    if (c0 + 1 > r0g + 8) sc[nj][3] = -1e30f;
                }
            }

            // ---- online softmax (rows r0g and r0g+8) ----
            float mx0 = -1e30f, mx1 = -1e30f;
#pragma unroll
            for (int nj = 0; nj < 8; ++nj) {
                mx0 = fmaxf(mx0, fmaxf(sc[nj][0], sc[nj][1]));
                mx1 = fmaxf(mx1, fmaxf(sc[nj][2], sc[nj][3]));
            }
            mx0 = fmaxf(mx0, __shfl_xor_sync(0xffffffffu, mx0, 1));
            mx0 = fmaxf(mx0, __shfl_xor_sync(0xffffffffu, mx0, 2));
            mx1 = fmaxf(mx1, __shfl_xor_sync(0xffffffffu, mx1, 1));
            mx1 = fmaxf(mx1, __shfl_xor_sync(0xffffffffu, mx1, 2));
            const float mn0 = fmaxf(m0, mx0), mn1 = fmaxf(m1, mx1);
            const float al0 = __expf(m0 - mn0), al1 = __expf(m1 - mn1);
            float rs0 = 0.f, rs1 = 0.f;
#pragma unroll
            for (int nj = 0; nj < 8; ++nj) {
                sc[nj][0] = __expf(sc[nj][0] - mn0);
                sc[nj][1] = __expf(sc[nj][1] - mn0);
                sc[nj][2] = __expf(sc[nj][2] - mn1);
                sc[nj][3] = __expf(sc[nj][3] - mn1);
                rs0 += sc[nj][0] + sc[nj][1];
                rs1 += sc[nj][2] + sc[nj][3];
            }
            rs0 += __shfl_xor_sync(0xffffffffu, rs0, 1);
            rs0 += __shfl_xor_sync(0xffffffffu, rs0, 2);
            rs1 += __shfl_xor_sync(0xffffffffu, rs1, 1);
            rs1 += __shfl_xor_sync(0xffffffffu, rs1, 2);
            l0 = l0 * al0 + rs0; l1 = l1 * al1 + rs1;
            m0 = mn0; m1 = mn1;
#pragma unroll
            for (int f = 0; f < 16; ++f) {
                o[f][0] *= al0; o[f][1] *= al0;
                o[f][2] *= al1; o[f][3] *= al1;
            }

            // ---- P -> bf16 hi/lo A-frags (C-frag pair == A-frag identity) ----
            uint32_t pfh[4][4], pfl[4][4];
#pragma unroll
            for (int tp = 0; tp < 4; ++tp) {
                const float* f0 = sc[2 * tp];
                const float* f1 = sc[2 * tp + 1];
                __nv_bfloat16 h0, h1, u0, u1;
#pragma unroll
                for (int half = 0; half < 2; ++half) {
                    const float a0 = half ? f1[0] : f0[0];
                    const float a1 = half ? f1[1] : f0[1];
                    const float a2 = half ? f1[2] : f0[2];
                    const float a3 = half ? f1[3] : f0[3];
                    bsplit(a0, h0, u0); bsplit(a1, h1, u1);
                    pfh[tp][half * 2] = (uint32_t)__bfloat16_as_ushort(h0) |
                                        ((uint32_t)__bfloat16_as_ushort(h1) << 16);
                    pfl[tp][half * 2] = (uint32_t)__bfloat16_as_ushort(u0) |
                                        ((uint32_t)__bfloat16_as_ushort(u1) << 16);
                    bsplit(a2, h0, u0); bsplit(a3, h1, u1);
                    pfh[tp][half * 2 + 1] = (uint32_t)__bfloat16_as_ushort(h0) |
                                            ((uint32_t)__bfloat16_as_ushort(h1) << 16);
                    pfl[tp][half * 2 + 1] = (uint32_t)__bfloat16_as_ushort(u0) |
                                            ((uint32_t)__bfloat16_as_ushort(u1) << 16);
                }
            }

            // ---- O += P V (3-term split), V via ldmatrix.trans ----
            const int g = lane >> 3;
#pragma unroll
            for (int ks = 0; ks < 4; ++ks) {
                uint32_t vh[16][2], vl[16][2];
                const int jrow = ks * 16 + (g & 1) * 8 + (lane & 7);
                const uint32_t cb = (uint32_t)((g >> 1) * 16);
#pragma unroll
                for (int n0 = 0; n0 < 8; ++n0) {
                    const uint32_t boff = (uint32_t)(jrow * FP_B + n0 * 32) + cb;
                    LDSM4T(vh[n0 * 2][0], vh[n0 * 2][1],
                           vh[n0 * 2 + 1][0], vh[n0 * 2 + 1][1], svh + boff);
                    LDSM4T(vl[n0 * 2][0], vl[n0 * 2][1],
                           vl[n0 * 2 + 1][0], vl[n0 * 2 + 1][1], svl + boff);
                }
#pragma unroll
                for (int nf = 0; nf < 16; ++nf) {
                    MMA_BF16(o[nf], pfh[ks], vh[nf]);
                    MMA_BF16(o[nf], pfh[ks], vl[nf]);
                    MMA_BF16(o[nf], pfl[ks], vh[nf]);
                }
            }
        }
        __syncthreads();
        buf ^= 1;
    }

    // ---- epilogue ----
    const float i0 = 1.f / l0, i1 = 1.f / l1;
    const int r0g = q0 + wm * 16 + (lane >> 2);
#pragma unroll
    for (int nf = 0; nf < 16; ++nf) {
        const int col = h * DH + nf * 8 + (lane & 3) * 2;
        float2 a, b;
        a.x = o[nf][0] * i0; a.y = o[nf][1] * i0;
        b.x = o[nf][2] * i1; b.y = o[nf][3] * i1;
        *(float2*)(Og + (size_t)r0g * HID + col) = a;
        *(float2*)(Og + (size_t)(r0g + 8) * HID + col) = b;
    }
}

// ====================================================================
// Residual + LayerNorm.
// ====================================================================
__device__ __forceinline__ float block_sum256(float v, float* red)
{
    __syncthreads();
    const int lane = threadIdx.x & 31;
    const int wp   = threadIdx.x >> 5;
#pragma unroll
    for (int o = 16; o; o >>= 1) v += __shfl_xor_sync(0xffffffffu, v, o);
    if (lane == 0) red[wp] = v;
    __syncthreads();
    if (wp == 0) {
        v = (lane < 8) ? red[lane] : 0.f;
#pragma unroll
        for (int o = 4; o; o >>= 1) v += __shfl_xor_sync(0xffffffffu, v, o);
        if (lane == 0) red[0] = v;
    }
    __syncthreads();
    return red[0];
}

__global__ __launch_bounds__(256) void ln_kernel(
    const float* __restrict__ O, const float* __restrict__ X,
    const float* __restrict__ w, const float* __restrict__ b,
    float* __restrict__ out)
{
    __shared__ float row[HID];
    __shared__ float red[8];
    const int s = blockIdx.x;
    const int tid = threadIdx.x;

    float lsum = 0.f;
    for (int c = tid * 4; c < HID; c += 1024) {
        const float4 o4 = *(const float4*)(O + s * HID + c);
        const float4 x4 = *(const float4*)(X + s * HID + c);
        float4 r;
        r.x = o4.x + x4.x; r.y = o4.y + x4.y;
        r.z = o4.z + x4.z; r.w = o4.w + x4.w;
        *(float4*)&row[c] = r;
        lsum += r.x + r.y + r.z + r.w;
    }
    const float mean = block_sum256(lsum, red) * (1.f / HID);

    float lsq = 0.f;
    for (int c = tid * 4; c < HID; c += 1024) {
        const float4 r = *(const float4*)&row[c];
        const float dx = r.x - mean, dy = r.y - mean;
        const float dz = r.z - mean, dw = r.w - mean;
        lsq += dx * dx + dy * dy + dz * dz + dw * dw;
    }
    const float var  = block_sum256(lsq, red) * (1.f / HID);
    const float rstd = rsqrtf(var + 1e-5f);

    for (int c = tid * 4; c < HID; c += 1024) {
        const float4 r  = *(const float4*)&row[c];
        const float4 w4 = *(const float4*)(w + c);
        const float4 b4 = *(const float4*)(b + c);
        float4 y;
        y.x = (r.x - mean) * rstd * w4.x + b4.x;
        y.y = (r.y - mean) * rstd * w4.y + b4.y;
        y.z = (r.z - mean) * rstd * w4.z + b4.z;
        y.w = (r.w - mean) * rstd * w4.w + b4.w;
        *(float4*)(out + s * HID + c) = y;
    }
}

// ====================================================================
// launch
// ====================================================================
extern "C" void kernel_launch(void* const* d_in, const int* in_sizes, int n_in,
                              void* d_out, int out_size)
{
    const float* x   = (const float*)d_in[0];
    const float* Wq  = (const float*)d_in[1];
    const float* bq  = (const float*)d_in[2];
    const float* Wk  = (const float*)d_in[3];
    const float* bk  = (const float*)d_in[4];
    const float* Wv  = (const float*)d_in[5];
    const float* bv  = (const float*)d_in[6];
    const float* Wo  = (const float*)d_in[7];
    const float* bo  = (const float*)d_in[8];
    const float* lnw = (const float*)d_in[9];
    const float* lnb = (const float*)d_in[10];
    float* out = (float*)d_out;

    float *q, *k, *v, *attn, *o;
    __nv_bfloat16 *xhi, *xlo, *whi, *wlo;
    __nv_bfloat16 *qhi, *qlo, *khi, *klo, *vhi, *vlo;
    cudaGetSymbolAddress((void**)&q,    g_q);
    cudaGetSymbolAddress((void**)&k,    g_k);
    cudaGetSymbolAddress((void**)&v,    g_v);
    cudaGetSymbolAddress((void**)&attn, g_attn);
    cudaGetSymbolAddress((void**)&o,    g_o);
    cudaGetSymbolAddress((void**)&xhi,  g_xhi);
    cudaGetSymbolAddress((void**)&xlo,  g_xlo);
    cudaGetSymbolAddress((void**)&whi,  g_whi);
    cudaGetSymbolAddress((void**)&wlo,  g_wlo);
    cudaGetSymbolAddress((void**)&qhi,  g_qhi);
    cudaGetSymbolAddress((void**)&qlo,  g_qlo);
    cudaGetSymbolAddress((void**)&khi,  g_khi);
    cudaGetSymbolAddress((void**)&klo,  g_klo);
    cudaGetSymbolAddress((void**)&vhi,  g_vhi);
    cudaGetSymbolAddress((void**)&vlo,  g_vlo);

    cudaFuncSetAttribute(gemm_bf16s,
                         cudaFuncAttributeMaxDynamicSharedMemorySize, GEMM_SMEM);
    cudaFuncSetAttribute(flash_tc,
                         cudaFuncAttributeMaxDynamicSharedMemorySize, FLASH_SMEM);

    const int N4  = SEQ * HID / 4;
    const int SGR = N4 / 256;

    // ---- QKV phase ----
    split_kernel<<<SGR, 256>>>(x,  xhi, xlo, N4);
    split_kernel<<<SGR, 256>>>(Wq, whi,                 wlo,                 N4);
    split_kernel<<<SGR, 256>>>(Wk, whi + HID * HID,     wlo + HID * HID,     N4);
    split_kernel<<<SGR, 256>>>(Wv, whi + 2 * HID * HID, wlo + 2 * HID * HID, N4);

    gemm_bf16s<<<dim3(HID / GBN, SEQ / GBM, 3), 256, GEMM_SMEM>>>(
        xhi, xlo, whi, wlo, bq, bk, bv, q, k, v);

    // ---- RoPE + bf16 splits for attention ----
    rope_split_kernel<<<SEQ, 1024>>>(q, k, qhi, qlo, khi, klo);
    split_kernel<<<SGR, 256>>>(v, vhi, vlo, N4);

    // ---- flash attention (tensor cores) ----
    flash_tc<<<dim3(SEQ / 128, NHEADS), 256, FLASH_SMEM>>>(
        qhi, qlo, khi, klo, vhi, vlo, attn);

    // ---- O projection ----
    split_kernel<<<SGR, 256>>>(attn, xhi, xlo, N4);
    split_kernel<<<SGR, 256>>>(Wo,   whi, wlo, N4);

    gemm_bf16s<<<dim3(HID / GBN, SEQ / GBM, 1), 256, GEMM_SMEM>>>(
        xhi, xlo, whi, wlo, bo, bo, bo, o, o, o);

    ln_kernel<<<SEQ, 256>>>(o, x, lnw, lnb, out);
}

// round 6
// speedup vs baseline: 3.0064x; 1.0538x over previous
#include <cuda_runtime.h>
#include <cuda_bf16.h>
#include <math.h>
#include <stdint.h>

#define SEQ    2048
#define HID    2048
#define NHEADS 16
#define DH     128
#define ATT_SCALE 0.08838834764831845f   // 1/sqrt(128)

// ---------------- scratch (device globals: allocation-free) ----------------
__device__ float g_q[SEQ * HID];
__device__ float g_k[SEQ * HID];
__device__ float g_o[SEQ * HID];
__device__ __nv_bfloat16 g_xhi[SEQ * HID];
__device__ __nv_bfloat16 g_xlo[SEQ * HID];
__device__ __nv_bfloat16 g_whi[3 * HID * HID];
__device__ __nv_bfloat16 g_wlo[3 * HID * HID];
__device__ __nv_bfloat16 g_qhi[SEQ * HID];
__device__ __nv_bfloat16 g_qlo[SEQ * HID];
__device__ __nv_bfloat16 g_khi[SEQ * HID];
__device__ __nv_bfloat16 g_klo[SEQ * HID];
__device__ __nv_bfloat16 g_vhi[SEQ * HID];
__device__ __nv_bfloat16 g_vlo[SEQ * HID];

// ====================================================================
// common helpers
// ====================================================================
__device__ __forceinline__ uint32_t smem_u32(const void* p) {
    uint32_t a;
    asm("{ .reg .u64 t; cvta.to.shared.u64 t, %1; cvt.u32.u64 %0, t; }"
        : "=r"(a) : "l"(p));
    return a;
}

__device__ __forceinline__ void bsplit(float x, __nv_bfloat16& h, __nv_bfloat16& l) {
    h = __float2bfloat16_rn(x);
    l = __float2bfloat16_rn(x - __bfloat162float(h));
}

__device__ __forceinline__ uint32_t pack2(__nv_bfloat16 a, __nv_bfloat16 b) {
    return (uint32_t)__bfloat16_as_ushort(a) |
           ((uint32_t)__bfloat16_as_ushort(b) << 16);
}

#define LDSM4(d0, d1, d2, d3, addr)                                        \
    asm volatile("ldmatrix.sync.aligned.m8n8.x4.shared.b16 "               \
                 "{%0,%1,%2,%3}, [%4];"                                    \
                 : "=r"(d0), "=r"(d1), "=r"(d2), "=r"(d3) : "r"(addr))

#define LDSM4T(d0, d1, d2, d3, addr)                                       \
    asm volatile("ldmatrix.sync.aligned.m8n8.x4.trans.shared.b16 "         \
                 "{%0,%1,%2,%3}, [%4];"                                    \
                 : "=r"(d0), "=r"(d1), "=r"(d2), "=r"(d3) : "r"(addr))

#define MMA_BF16(acc, a, b)                                                \
    asm volatile("mma.sync.aligned.m16n8k16.row.col.f32.bf16.bf16.f32 "    \
                 "{%0,%1,%2,%3}, {%4,%5,%6,%7}, {%8,%9}, {%0,%1,%2,%3};"   \
                 : "+f"((acc)[0]), "+f"((acc)[1]), "+f"((acc)[2]),         \
                   "+f"((acc)[3])                                          \
                 : "r"((a)[0]), "r"((a)[1]), "r"((a)[2]), "r"((a)[3]),     \
                   "r"((b)[0]), "r"((b)[1]))

#define CPA16(dst, src)                                                    \
    asm volatile("cp.async.cg.shared.global [%0], [%1], 16;"               \
                 :: "r"(dst), "l"(src))

// ====================================================================
// fp32 -> bf16 hi/lo split
// ====================================================================
__global__ __launch_bounds__(256) void split_kernel(
    const float* __restrict__ in, __nv_bfloat16* __restrict__ hi,
    __nv_bfloat16* __restrict__ lo, int n4)
{
    const int i = blockIdx.x * 256 + threadIdx.x;
    if (i >= n4) return;
    const float4 v = *(const float4*)(in + i * 4);
    __nv_bfloat16 h0, h1, h2, h3, l0, l1, l2, l3;
    bsplit(v.x, h0, l0); bsplit(v.y, h1, l1);
    bsplit(v.z, h2, l2); bsplit(v.w, h3, l3);
    uint2 ph, pl;
    ph.x = pack2(h0, h1); ph.y = pack2(h2, h3);
    pl.x = pack2(l0, l1); pl.y = pack2(l2, l3);
    *(uint2*)(hi + i * 4) = ph;
    *(uint2*)(lo + i * 4) = pl;
}

// ====================================================================
// RoPE + bf16 split for q,k
// ====================================================================
__global__ __launch_bounds__(1024) void rope_split_kernel(
    const float* __restrict__ q, const float* __restrict__ k,
    __nv_bfloat16* __restrict__ qhi, __nv_bfloat16* __restrict__ qlo,
    __nv_bfloat16* __restrict__ khi, __nv_bfloat16* __restrict__ klo)
{
    const int s = blockIdx.x;
    const int t = threadIdx.x;
    const int h = t >> 6;
    const int i = t & 63;

    const float invf = (float)pow(10000.0, -(double)(2 * i) / 128.0);
    const float ang  = (float)s * invf;
    const float c  = (float)cos((double)ang);
    const float sn = (float)sin((double)ang);

    const int base = s * HID + h * DH + i;
    __nv_bfloat16 hh, ll;

    float a = q[base], b = q[base + 64];
    float x0 = a * c - b * sn, x1 = b * c + a * sn;
    bsplit(x0, hh, ll); qhi[base]      = hh; qlo[base]      = ll;
    bsplit(x1, hh, ll); qhi[base + 64] = hh; qlo[base + 64] = ll;

    a = k[base];  b = k[base + 64];
    x0 = a * c - b * sn; x1 = b * c + a * sn;
    bsplit(x0, hh, ll); khi[base]      = hh; klo[base]      = ll;
    bsplit(x1, hh, ll); khi[base + 64] = hh; klo[base + 64] = ll;
}

// ====================================================================
// bf16 mma.sync GEMM, 3-term split, 2 CTAs/SM.
// z==2 (V projection) emits bf16 hi/lo directly; else fp32 + bias.
// ====================================================================
#define GBM 128
#define GBN 128
#define GBK 32
#define GKIT (HID / GBK)
#define PITCH 40
#define TILE_B (128 * PITCH * 2)
#define OFF_AHI 0
#define OFF_ALO (1 * TILE_B)
#define OFF_BHI (2 * TILE_B)
#define OFF_BLO (3 * TILE_B)
#define STAGE_B (4 * TILE_B)
#define GEMM_SMEM (2 * STAGE_B)

__global__ __launch_bounds__(256, 2) void gemm_bf16s(
    const __nv_bfloat16* __restrict__ Ahi, const __nv_bfloat16* __restrict__ Alo,
    const __nv_bfloat16* __restrict__ Whi, const __nv_bfloat16* __restrict__ Wlo,
    const float* __restrict__ b0, const float* __restrict__ b1,
    const float* __restrict__ b2,
    float* __restrict__ C0, float* __restrict__ C1,
    __nv_bfloat16* __restrict__ Vhi, __nv_bfloat16* __restrict__ Vlo)
{
    extern __shared__ char sm[];
    const uint32_t sbase = smem_u32(sm);

    const int z = blockIdx.z;
    const __nv_bfloat16* Bhi = Whi + (size_t)z * HID * HID;
    const __nv_bfloat16* Blo = Wlo + (size_t)z * HID * HID;
    const float* bias = (z == 0) ? b0 : (z == 1 ? b1 : b2);

    const int tid  = threadIdx.x;
    const int lane = tid & 31;
    const int wid  = tid >> 5;
    const int wm   = wid & 3;
    const int wn   = wid >> 2;
    const int bm = blockIdx.y * GBM;
    const int bn = blockIdx.x * GBN;

    const int lrow = tid >> 1;
    const int lcol = (tid & 1) * 16;
    const uint32_t sdst = (uint32_t)(lrow * (PITCH * 2) + lcol * 2);
    const __nv_bfloat16* pAhi = Ahi + (size_t)(bm + lrow) * HID + lcol;
    const __nv_bfloat16* pAlo = Alo + (size_t)(bm + lrow) * HID + lcol;
    const __nv_bfloat16* pBhi = Bhi + (size_t)(bn + lrow) * HID + lcol;
    const __nv_bfloat16* pBlo = Blo + (size_t)(bn + lrow) * HID + lcol;

    float acc[2][8][4];
#pragma unroll
    for (int mi = 0; mi < 2; ++mi)
#pragma unroll
        for (int nj = 0; nj < 8; ++nj)
#pragma unroll
            for (int c = 0; c < 4; ++c) acc[mi][nj][c] = 0.f;

    auto load_stage = [&](int kt, int buf) {
        const int k0 = kt * GBK;
        const uint32_t s = sbase + buf * STAGE_B + sdst;
        CPA16(s + OFF_AHI,      pAhi + k0);
        CPA16(s + OFF_AHI + 16, pAhi + k0 + 8);
        CPA16(s + OFF_ALO,      pAlo + k0);
        CPA16(s + OFF_ALO + 16, pAlo + k0 + 8);
        CPA16(s + OFF_BHI,      pBhi + k0);
        CPA16(s + OFF_BHI + 16, pBhi + k0 + 8);
        CPA16(s + OFF_BLO,      pBlo + k0);
        CPA16(s + OFF_BLO + 16, pBlo + k0 + 8);
    };

    load_stage(0, 0);
    asm volatile("cp.async.commit_group;");

    int buf = 0;
    for (int kt = 0; kt < GKIT; ++kt) {
        if (kt + 1 < GKIT) load_stage(kt + 1, buf ^ 1);
        asm volatile("cp.async.commit_group;");
        asm volatile("cp.async.wait_group 1;");
        __syncthreads();

        const uint32_t sA_hi = sbase + buf * STAGE_B + OFF_AHI;
        const uint32_t sA_lo = sbase + buf * STAGE_B + OFF_ALO;
        const uint32_t sB_hi = sbase + buf * STAGE_B + OFF_BHI;
        const uint32_t sB_lo = sbase + buf * STAGE_B + OFF_BLO;

#pragma unroll
        for (int kk = 0; kk < 2; ++kk) {
            uint32_t a_hi[2][4], a_lo[2][4];
            const int r16 = lane & 15;
            const int ksel = lane >> 4;
#pragma unroll
            for (int mi = 0; mi < 2; ++mi) {
                const uint32_t off =
                    (uint32_t)((wm * 32 + mi * 16 + r16) * (PITCH * 2) +
                               (kk * 2 + ksel) * 16);
                LDSM4(a_hi[mi][0], a_hi[mi][1], a_hi[mi][2], a_hi[mi][3],
                      sA_hi + off);
                LDSM4(a_lo[mi][0], a_lo[mi][1], a_lo[mi][2], a_lo[mi][3],
                      sA_lo + off);
            }
            const int q  = lane >> 3;
            const int rr = lane & 7;
            // B frags loaded per-a2 (8 live regs) to fit 128-reg budget
#pragma unroll
            for (int a2 = 0; a2 < 4; ++a2) {
                uint32_t bh[4], bl[4];
                const int row = wn * 64 + a2 * 16 + (q >> 1) * 8 + rr;
                const uint32_t off =
                    (uint32_t)(row * (PITCH * 2) + (kk * 2 + (q & 1)) * 16);
                LDSM4(bh[0], bh[1], bh[2], bh[3], sB_hi + off);
                LDSM4(bl[0], bl[1], bl[2], bl[3], sB_lo + off);
#pragma unroll
                for (int mi = 0; mi < 2; ++mi) {
                    MMA_BF16(acc[mi][a2 * 2],     a_hi[mi], bh);
                    MMA_BF16(acc[mi][a2 * 2],     a_hi[mi], bl);
                    MMA_BF16(acc[mi][a2 * 2],     a_lo[mi], bh);
                    MMA_BF16(acc[mi][a2 * 2 + 1], a_hi[mi], bh + 2);
                    MMA_BF16(acc[mi][a2 * 2 + 1], a_hi[mi], bl + 2);
                    MMA_BF16(acc[mi][a2 * 2 + 1], a_lo[mi], bh + 2);
                }
            }
        }
        __syncthreads();
        buf ^= 1;
    }

    const int trow = lane >> 2;
    const int tcol = (lane & 3) * 2;
    if (z == 2) {
        // V projection: emit bf16 hi/lo directly
#pragma unroll
        for (int mi = 0; mi < 2; ++mi) {
            const int r = bm + wm * 32 + mi * 16 + trow;
#pragma unroll
            for (int nj = 0; nj < 8; ++nj) {
                const int c = bn + wn * 64 + nj * 8 + tcol;
                const float bx = bias[c], by = bias[c + 1];
                __nv_bfloat16 h0, h1, l0, l1;
                bsplit(acc[mi][nj][0] + bx, h0, l0);
                bsplit(acc[mi][nj][1] + by, h1, l1);
                *(uint32_t*)(Vhi + (size_t)r * HID + c) = pack2(h0, h1);
                *(uint32_t*)(Vlo + (size_t)r * HID + c) = pack2(l0, l1);
                bsplit(acc[mi][nj][2] + bx, h0, l0);
                bsplit(acc[mi][nj][3] + by, h1, l1);
                *(uint32_t*)(Vhi + (size_t)(r + 8) * HID + c) = pack2(h0, h1);
                *(uint32_t*)(Vlo + (size_t)(r + 8) * HID + c) = pack2(l0, l1);
            }
        }
    } else {
        float* C = (z == 0) ? C0 : C1;
#pragma unroll
        for (int mi = 0; mi < 2; ++mi) {
            const int r = bm + wm * 32 + mi * 16 + trow;
#pragma unroll
            for (int nj = 0; nj < 8; ++nj) {
                const int c = bn + wn * 64 + nj * 8 + tcol;
                const float bx = bias[c], by = bias[c + 1];
                float2 o;
                o.x = acc[mi][nj][0] + bx; o.y = acc[mi][nj][1] + by;
                *(float2*)(C + (size_t)r * HID + c) = o;
                o.x = acc[mi][nj][2] + bx; o.y = acc[mi][nj][3] + by;
                *(float2*)(C + (size_t)(r + 8) * HID + c) = o;
            }
        }
    }
}

// ====================================================================
// Flash attention on bf16 mma.sync (3xBF16 split).
// Epilogue writes attn as bf16 hi/lo (feeds O-projection GEMM directly).
// ====================================================================
#define FP_B 272
#define QTILE_FB (128 * FP_B)
#define KVTILE_FB (64 * FP_B)
#define FKV0 (2 * QTILE_FB)
#define FKSTG (4 * KVTILE_FB)
#define FLASH_SMEM (FKV0 + 2 * FKSTG)

__global__ __launch_bounds__(256, 1) void flash_tc(
    const __nv_bfloat16* __restrict__ qhi, const __nv_bfloat16* __restrict__ qlo,
    const __nv_bfloat16* __restrict__ khi, const __nv_bfloat16* __restrict__ klo,
    const __nv_bfloat16* __restrict__ vhi, const __nv_bfloat16* __restrict__ vlo,
    __nv_bfloat16* __restrict__ Ohi, __nv_bfloat16* __restrict__ Olo)
{
    extern __shared__ char sm[];
    const uint32_t sb = smem_u32(sm);
    const int h  = blockIdx.y;
    const int qb = blockIdx.x;
    const int q0 = qb * 128;
    const int tid = threadIdx.x, lane = tid & 31, wm = tid >> 5;

    {
        const __nv_bfloat16* ph = qhi + (size_t)q0 * HID + h * DH;
        const __nv_bfloat16* pl = qlo + (size_t)q0 * HID + h * DH;
#pragma unroll
        for (int i = 0; i < 8; ++i) {
            const int idx = tid + i * 256, row = idx >> 4, c = idx & 15;
            const uint32_t d = (uint32_t)(row * FP_B + c * 16);
            CPA16(sb + d,            ph + (size_t)row * HID + c * 8);
            CPA16(sb + QTILE_FB + d, pl + (size_t)row * HID + c * 8);
        }
    }

    auto load_kv = [&](int t, int b) {
        const int j0 = t * 64;
        const uint32_t s = sb + FKV0 + b * FKSTG;
#pragma unroll
        for (int i = 0; i < 4; ++i) {
            const int idx = tid + i * 256, row = idx >> 4, c = idx & 15;
            const uint32_t d = (uint32_t)(row * FP_B + c * 16);
            const size_t g = (size_t)(j0 + row) * HID + h * DH + c * 8;
            CPA16(s + 0 * KVTILE_FB + d, khi + g);
            CPA16(s + 1 * KVTILE_FB + d, klo + g);
            CPA16(s + 2 * KVTILE_FB + d, vhi + g);
            CPA16(s + 3 * KVTILE_FB + d, vlo + g);
        }
    };

    load_kv(0, 0);
    asm volatile("cp.async.commit_group;");

    float o[16][4];
#pragma unroll
    for (int f = 0; f < 16; ++f)
#pragma unroll
        for (int c = 0; c < 4; ++c) o[f][c] = 0.f;
    float m0 = -1e30f, m1 = -1e30f, l0 = 0.f, l1 = 0.f;

    const int ntiles = 2 * qb + 2;
    int buf = 0;
    for (int t = 0; t < ntiles; ++t) {
        if (t + 1 < ntiles) load_kv(t + 1, buf ^ 1);
        asm volatile("cp.async.commit_group;");
        asm volatile("cp.async.wait_group 1;");
        __syncthreads();

        const int j0 = t * 64;
        const uint32_t skh = sb + FKV0 + buf * FKSTG;
        const uint32_t skl = skh + KVTILE_FB;
        const uint32_t svh = skh + 2 * KVTILE_FB;
        const uint32_t svl = skh + 3 * KVTILE_FB;

        if (j0 <= q0 + wm * 16 + 15) {
            float sc[8][4];
#pragma unroll
            for (int nj = 0; nj < 8; ++nj)
#pragma unroll
                for (int c = 0; c < 4; ++c) sc[nj][c] = 0.f;

            const int r16 = lane & 15, ksel = lane >> 4;
            const int qq = lane >> 3, rr = lane & 7;
#pragma unroll
            for (int kk = 0; kk < 8; ++kk) {
                uint32_t ah[4], al[4];
                const uint32_t aoff =
                    (uint32_t)((wm * 16 + r16) * FP_B + (kk * 2 + ksel) * 16);
                LDSM4(ah[0], ah[1], ah[2], ah[3], sb + aoff);
                LDSM4(al[0], al[1], al[2], al[3], sb + QTILE_FB + aoff);
#pragma unroll
                for (int a2 = 0; a2 < 4; ++a2) {
                    uint32_t bh[4], bl[4];
                    const uint32_t boff =
                        (uint32_t)((a2 * 16 + (qq >> 1) * 8 + rr) * FP_B +
                                   (kk * 2 + (qq & 1)) * 16);
                    LDSM4(bh[0], bh[1], bh[2], bh[3], skh + boff);
                    LDSM4(bl[0], bl[1], bl[2], bl[3], skl + boff);
                    MMA_BF16(sc[a2 * 2],     ah, bh);
                    MMA_BF16(sc[a2 * 2],     ah, bl);
                    MMA_BF16(sc[a2 * 2],     al, bh);
                    MMA_BF16(sc[a2 * 2 + 1], ah, bh + 2);
                    MMA_BF16(sc[a2 * 2 + 1], ah, bl + 2);
                    MMA_BF16(sc[a2 * 2 + 1], al, bh + 2);
                }
            }

            const int r0g = q0 + wm * 16 + (lane >> 2);
            const bool needMask = (j0 + 63 > q0 + wm * 16);
#pragma unroll
            for (int nj = 0; nj < 8; ++nj) {
                const int c0 = j0 + nj * 8 + (lane & 3) * 2;
                sc[nj][0] *= ATT_SCALE; sc[nj][1] *= ATT_SCALE;
                sc[nj][2] *= ATT_SCALE; sc[nj][3] *= ATT_SCALE;
                if (needMask) {
                    if (c0     > r0g)     sc[nj][0] = -1e30f;
                    if (c0 + 1 > r0g)     sc[nj][1] = -1e30f;
                    if (c0     > r0g + 8) sc[nj][2] = -1e30f;
                    if (c0 + 1 > r0g + 8) sc[nj][3] = -1e30f;
                }
            }

            float mx0 = -1e30f, mx1 = -1e30f;
#pragma unroll
            for (int nj = 0; nj < 8; ++nj) {
                mx0 = fmaxf(mx0, fmaxf(sc[nj][0], sc[nj][1]));
                mx1 = fmaxf(mx1, fmaxf(sc[nj][2], sc[nj][3]));
            }
            mx0 = fmaxf(mx0, __shfl_xor_sync(0xffffffffu, mx0, 1));
            mx0 = fmaxf(mx0, __shfl_xor_sync(0xffffffffu, mx0, 2));
            mx1 = fmaxf(mx1, __shfl_xor_sync(0xffffffffu, mx1, 1));
            mx1 = fmaxf(mx1, __shfl_xor_sync(0xffffffffu, mx1, 2));
            const float mn0 = fmaxf(m0, mx0), mn1 = fmaxf(m1, mx1);
            const float al0 = __expf(m0 - mn0), al1 = __expf(m1 - mn1);
            float rs0 = 0.f, rs1 = 0.f;
#pragma unroll
            for (int nj = 0; nj < 8; ++nj) {
                sc[nj][0] = __expf(sc[nj][0] - mn0);
                sc[nj][1] = __expf(sc[nj][1] - mn0);
                sc[nj][2] = __expf(sc[nj][2] - mn1);
                sc[nj][3] = __expf(sc[nj][3] - mn1);
                rs0 += sc[nj][0] + sc[nj][1];
                rs1 += sc[nj][2] + sc[nj][3];
            }
            rs0 += __shfl_xor_sync(0xffffffffu, rs0, 1);
            rs0 += __shfl_xor_sync(0xffffffffu, rs0, 2);
            rs1 += __shfl_xor_sync(0xffffffffu, rs1, 1);
            rs1 += __shfl_xor_sync(0xffffffffu, rs1, 2);
            l0 = l0 * al0 + rs0; l1 = l1 * al1 + rs1;
            m0 = mn0; m1 = mn1;
#pragma unroll
            for (int f = 0; f < 16; ++f) {
                o[f][0] *= al0; o[f][1] *= al0;
                o[f][2] *= al1; o[f][3] *= al1;
            }

            uint32_t pfh[4][4], pfl[4][4];
#pragma unroll
            for (int tp = 0; tp < 4; ++tp) {
                const float* f0 = sc[2 * tp];
                const float* f1 = sc[2 * tp + 1];
                __nv_bfloat16 h0, h1, u0, u1;
#pragma unroll
                for (int half = 0; half < 2; ++half) {
                    const float a0 = half ? f1[0] : f0[0];
                    const float a1 = half ? f1[1] : f0[1];
                    const float a2 = half ? f1[2] : f0[2];
                    const float a3 = half ? f1[3] : f0[3];
                    bsplit(a0, h0, u0); bsplit(a1, h1, u1);
                    pfh[tp][half * 2] = pack2(h0, h1);
                    pfl[tp][half * 2] = pack2(u0, u1);
                    bsplit(a2, h0, u0); bsplit(a3, h1, u1);
                    pfh[tp][half * 2 + 1] = pack2(h0, h1);
                    pfl[tp][half * 2 + 1] = pack2(u0, u1);
                }
            }

            const int g = lane >> 3;
#pragma unroll
            for (int ks = 0; ks < 4; ++ks) {
                uint32_t vh[16][2], vl[16][2];
                const int jrow = ks * 16 + (g & 1) * 8 + (lane & 7);
                const uint32_t cb = (uint32_t)((g >> 1) * 16);
#pragma unroll
                for (int n0 = 0; n0 < 8; ++n0) {
                    const uint32_t boff = (uint32_t)(jrow * FP_B + n0 * 32) + cb;
                    LDSM4T(vh[n0 * 2][0], vh[n0 * 2][1],
                           vh[n0 * 2 + 1][0], vh[n0 * 2 + 1][1], svh + boff);
                    LDSM4T(vl[n0 * 2][0], vl[n0 * 2][1],
                           vl[n0 * 2 + 1][0], vl[n0 * 2 + 1][1], svl + boff);
                }
#pragma unroll
                for (int nf = 0; nf < 16; ++nf) {
                    MMA_BF16(o[nf], pfh[ks], vh[nf]);
                    MMA_BF16(o[nf], pfh[ks], vl[nf]);
                    MMA_BF16(o[nf], pfl[ks], vh[nf]);
                }
            }
        }
        __syncthreads();
        buf ^= 1;
    }

    // epilogue: normalize, split to bf16 hi/lo, store
    const float i0 = 1.f / l0, i1 = 1.f / l1;
    const int r0g = q0 + wm * 16 + (lane >> 2);
#pragma unroll
    for (int nf = 0; nf < 16; ++nf) {
        const int col = h * DH + nf * 8 + (lane & 3) * 2;
        __nv_bfloat16 h0, h1, u0, u1;
        bsplit(o[nf][0] * i0, h0, u0);
        bsplit(o[nf][1] * i0, h1, u1);
        *(uint32_t*)(Ohi + (size_t)r0g * HID + col) = pack2(h0, h1);
        *(uint32_t*)(Olo + (size_t)r0g * HID + col) = pack2(u0, u1);
        bsplit(o[nf][2] * i1, h0, u0);
        bsplit(o[nf][3] * i1, h1, u1);
        *(uint32_t*)(Ohi + (size_t)(r0g + 8) * HID + col) = pack2(h0, h1);
        *(uint32_t*)(Olo + (size_t)(r0g + 8) * HID + col) = pack2(u0, u1);
    }
}

// ====================================================================
// Residual + LayerNorm.
// ====================================================================
__device__ __forceinline__ float block_sum256(float v, float* red)
{
    __syncthreads();
    const int lane = threadIdx.x & 31;
    const int wp   = threadIdx.x >> 5;
#pragma unroll
    for (int o = 16; o; o >>= 1) v += __shfl_xor_sync(0xffffffffu, v, o);
    if (lane == 0) red[wp] = v;
    __syncthreads();
    if (wp == 0) {
        v = (lane < 8) ? red[lane] : 0.f;
#pragma unroll
        for (int o = 4; o; o >>= 1) v += __shfl_xor_sync(0xffffffffu, v, o);
        if (lane == 0) red[0] = v;
    }
    __syncthreads();
    return red[0];
}

__global__ __launch_bounds__(256) void ln_kernel(
    const float* __restrict__ O, const float* __restrict__ X,
    const float* __restrict__ w, const float* __restrict__ b,
    float* __restrict__ out)
{
    __shared__ float row[HID];
    __shared__ float red[8];
    const int s = blockIdx.x;
    const int tid = threadIdx.x;

    float lsum = 0.f;
    for (int c = tid * 4; c < HID; c += 1024) {
        const float4 o4 = *(const float4*)(O + s * HID + c);
        const float4 x4 = *(const float4*)(X + s * HID + c);
        float4 r;
        r.x = o4.x + x4.x; r.y = o4.y + x4.y;
        r.z = o4.z + x4.z; r.w = o4.w + x4.w;
        *(float4*)&row[c] = r;
        lsum += r.x + r.y + r.z + r.w;
    }
    const float mean = block_sum256(lsum, red) * (1.f / HID);

    float lsq = 0.f;
    for (int c = tid * 4; c < HID; c += 1024) {
        const float4 r = *(const float4*)&row[c];
        const float dx = r.x - mean, dy = r.y - mean;
        const float dz = r.z - mean, dw = r.w - mean;
        lsq += dx * dx + dy * dy + dz * dz + dw * dw;
    }
    const float var  = block_sum256(lsq, red) * (1.f / HID);
    const float rstd = rsqrtf(var + 1e-5f);

    for (int c = tid * 4; c < HID; c += 1024) {
        const float4 r  = *(const float4*)&row[c];
        const float4 w4 = *(const float4*)(w + c);
        const float4 b4 = *(const float4*)(b + c);
        float4 y;
        y.x = (r.x - mean) * rstd * w4.x + b4.x;
        y.y = (r.y - mean) * rstd * w4.y + b4.y;
        y.z = (r.z - mean) * rstd * w4.z + b4.z;
        y.w = (r.w - mean) * rstd * w4.w + b4.w;
        *(float4*)(out + s * HID + c) = y;
    }
}

// ====================================================================
// launch
// ====================================================================
extern "C" void kernel_launch(void* const* d_in, const int* in_sizes, int n_in,
                              void* d_out, int out_size)
{
    const float* x   = (const float*)d_in[0];
    const float* Wq  = (const float*)d_in[1];
    const float* bq  = (const float*)d_in[2];
    const float* Wk  = (const float*)d_in[3];
    const float* bk  = (const float*)d_in[4];
    const float* Wv  = (const float*)d_in[5];
    const float* bv  = (const float*)d_in[6];
    const float* Wo  = (const float*)d_in[7];
    const float* bo  = (const float*)d_in[8];
    const float* lnw = (const float*)d_in[9];
    const float* lnb = (const float*)d_in[10];
    float* out = (float*)d_out;

    float *q, *k, *o;
    __nv_bfloat16 *xhi, *xlo, *whi, *wlo;
    __nv_bfloat16 *qhi, *qlo, *khi, *klo, *vhi, *vlo;
    cudaGetSymbolAddress((void**)&q,    g_q);
    cudaGetSymbolAddress((void**)&k,    g_k);
    cudaGetSymbolAddress((void**)&o,    g_o);
    cudaGetSymbolAddress((void**)&xhi,  g_xhi);
    cudaGetSymbolAddress((void**)&xlo,  g_xlo);
    cudaGetSymbolAddress((void**)&whi,  g_whi);
    cudaGetSymbolAddress((void**)&wlo,  g_wlo);
    cudaGetSymbolAddress((void**)&qhi,  g_qhi);
    cudaGetSymbolAddress((void**)&qlo,  g_qlo);
    cudaGetSymbolAddress((void**)&khi,  g_khi);
    cudaGetSymbolAddress((void**)&klo,  g_klo);
    cudaGetSymbolAddress((void**)&vhi,  g_vhi);
    cudaGetSymbolAddress((void**)&vlo,  g_vlo);

    cudaFuncSetAttribute(gemm_bf16s,
                         cudaFuncAttributeMaxDynamicSharedMemorySize, GEMM_SMEM);
    cudaFuncSetAttribute(flash_tc,
                         cudaFuncAttributeMaxDynamicSharedMemorySize, FLASH_SMEM);

    const int N4  = SEQ * HID / 4;
    const int SGR = N4 / 256;

    // ---- splits for QKV ----
    split_kernel<<<SGR, 256>>>(x,  xhi, xlo, N4);
    split_kernel<<<SGR, 256>>>(Wq, whi,                 wlo,                 N4);
    split_kernel<<<SGR, 256>>>(Wk, whi + HID * HID,     wlo + HID * HID,     N4);
    split_kernel<<<SGR, 256>>>(Wv, whi + 2 * HID * HID, wlo + 2 * HID * HID, N4);

    // ---- QKV projections (z==2 emits bf16 V directly) ----
    gemm_bf16s<<<dim3(HID / GBN, SEQ / GBM, 3), 256, GEMM_SMEM>>>(
        xhi, xlo, whi, wlo, bq, bk, bv, q, k, vhi, vlo);

    rope_split_kernel<<<SEQ, 1024>>>(q, k, qhi, qlo, khi, klo);

    // ---- flash attention (writes attn as bf16 hi/lo into xhi/xlo) ----
    flash_tc<<<dim3(SEQ / 128, NHEADS), 256, FLASH_SMEM>>>(
        qhi, qlo, khi, klo, vhi, vlo, xhi, xlo);

    // ---- O projection ----
    split_kernel<<<SGR, 256>>>(Wo, whi, wlo, N4);
    gemm_bf16s<<<dim3(HID / GBN, SEQ / GBM, 1), 256, GEMM_SMEM>>>(
        xhi, xlo, whi, wlo, bo, bo, bo, o, o, vhi, vlo);

    ln_kernel<<<SEQ, 256>>>(o, x, lnw, lnb, out);
}

// round 7
// speedup vs baseline: 3.1382x; 1.0438x over previous
#include <cuda_runtime.h>
#include <cuda_bf16.h>
#include <math.h>
#include <stdint.h>

#define SEQ    2048
#define HID    2048
#define NHEADS 16
#define DH     128
#define ATT_SCALE 0.08838834764831845f   // 1/sqrt(128)

// ---------------- scratch (device globals: allocation-free) ----------------
__device__ float g_q[SEQ * HID];
__device__ float g_k[SEQ * HID];
__device__ float g_o[SEQ * HID];
__device__ __nv_bfloat16 g_xhi[SEQ * HID];
__device__ __nv_bfloat16 g_xlo[SEQ * HID];
__device__ __nv_bfloat16 g_whi[4 * HID * HID];
__device__ __nv_bfloat16 g_wlo[4 * HID * HID];
__device__ __nv_bfloat16 g_qhi[SEQ * HID];
__device__ __nv_bfloat16 g_qlo[SEQ * HID];
__device__ __nv_bfloat16 g_khi[SEQ * HID];
__device__ __nv_bfloat16 g_klo[SEQ * HID];
__device__ __nv_bfloat16 g_vhi[SEQ * HID];
__device__ __nv_bfloat16 g_vlo[SEQ * HID];

// ====================================================================
// common helpers
// ====================================================================
__device__ __forceinline__ uint32_t smem_u32(const void* p) {
    uint32_t a;
    asm("{ .reg .u64 t; cvta.to.shared.u64 t, %1; cvt.u32.u64 %0, t; }"
        : "=r"(a) : "l"(p));
    return a;
}

__device__ __forceinline__ void bsplit(float x, __nv_bfloat16& h, __nv_bfloat16& l) {
    h = __float2bfloat16_rn(x);
    l = __float2bfloat16_rn(x - __bfloat162float(h));
}

__device__ __forceinline__ uint32_t pack2(__nv_bfloat16 a, __nv_bfloat16 b) {
    return (uint32_t)__bfloat16_as_ushort(a) |
           ((uint32_t)__bfloat16_as_ushort(b) << 16);
}

#define LDSM4(d0, d1, d2, d3, addr)                                        \
    asm volatile("ldmatrix.sync.aligned.m8n8.x4.shared.b16 "               \
                 "{%0,%1,%2,%3}, [%4];"                                    \
                 : "=r"(d0), "=r"(d1), "=r"(d2), "=r"(d3) : "r"(addr))

#define LDSM4T(d0, d1, d2, d3, addr)                                       \
    asm volatile("ldmatrix.sync.aligned.m8n8.x4.trans.shared.b16 "         \
                 "{%0,%1,%2,%3}, [%4];"                                    \
                 : "=r"(d0), "=r"(d1), "=r"(d2), "=r"(d3) : "r"(addr))

#define MMA_BF16(acc, a, b)                                                \
    asm volatile("mma.sync.aligned.m16n8k16.row.col.f32.bf16.bf16.f32 "    \
                 "{%0,%1,%2,%3}, {%4,%5,%6,%7}, {%8,%9}, {%0,%1,%2,%3};"   \
                 : "+f"((acc)[0]), "+f"((acc)[1]), "+f"((acc)[2]),         \
                   "+f"((acc)[3])                                          \
                 : "r"((a)[0]), "r"((a)[1]), "r"((a)[2]), "r"((a)[3]),     \
                   "r"((b)[0]), "r"((b)[1]))

#define CPA16(dst, src)                                                    \
    asm volatile("cp.async.cg.shared.global [%0], [%1], 16;"               \
                 :: "r"(dst), "l"(src))

// ====================================================================
// fp32 -> bf16 hi/lo split for x + 4 weight matrices, one launch.
// ====================================================================
__global__ __launch_bounds__(256) void split5_kernel(
    const float* __restrict__ x,
    const float* __restrict__ wq, const float* __restrict__ wk,
    const float* __restrict__ wv, const float* __restrict__ wo,
    __nv_bfloat16* __restrict__ xhi, __nv_bfloat16* __restrict__ xlo,
    __nv_bfloat16* __restrict__ whi, __nv_bfloat16* __restrict__ wlo,
    int n4)
{
    const size_t W = (size_t)HID * HID;
    const float* in;
    __nv_bfloat16 *hi, *lo;
    switch (blockIdx.y) {
        case 0:  in = x;  hi = xhi;         lo = xlo;         break;
        case 1:  in = wq; hi = whi;         lo = wlo;         break;
        case 2:  in = wk; hi = whi + W;     lo = wlo + W;     break;
        case 3:  in = wv; hi = whi + 2 * W; lo = wlo + 2 * W; break;
        default: in = wo; hi = whi + 3 * W; lo = wlo + 3 * W; break;
    }
    const int i = blockIdx.x * 256 + threadIdx.x;
    if (i >= n4) return;
    const float4 v = *(const float4*)(in + i * 4);
    __nv_bfloat16 h0, h1, h2, h3, l0, l1, l2, l3;
    bsplit(v.x, h0, l0); bsplit(v.y, h1, l1);
    bsplit(v.z, h2, l2); bsplit(v.w, h3, l3);
    uint2 ph, pl;
    ph.x = pack2(h0, h1); ph.y = pack2(h2, h3);
    pl.x = pack2(l0, l1); pl.y = pack2(l2, l3);
    *(uint2*)(hi + i * 4) = ph;
    *(uint2*)(lo + i * 4) = pl;
}

// ====================================================================
// RoPE + bf16 split for q,k
// ====================================================================
__global__ __launch_bounds__(1024) void rope_split_kernel(
    const float* __restrict__ q, const float* __restrict__ k,
    __nv_bfloat16* __restrict__ qhi, __nv_bfloat16* __restrict__ qlo,
    __nv_bfloat16* __restrict__ khi, __nv_bfloat16* __restrict__ klo)
{
    const int s = blockIdx.x;
    const int t = threadIdx.x;
    const int h = t >> 6;
    const int i = t & 63;

    const float invf = (float)pow(10000.0, -(double)(2 * i) / 128.0);
    const float ang  = (float)s * invf;
    const float c  = (float)cos((double)ang);
    const float sn = (float)sin((double)ang);

    const int base = s * HID + h * DH + i;
    __nv_bfloat16 hh, ll;

    float a = q[base], b = q[base + 64];
    float x0 = a * c - b * sn, x1 = b * c + a * sn;
    bsplit(x0, hh, ll); qhi[base]      = hh; qlo[base]      = ll;
    bsplit(x1, hh, ll); qhi[base + 64] = hh; qlo[base + 64] = ll;

    a = k[base];  b = k[base + 64];
    x0 = a * c - b * sn; x1 = b * c + a * sn;
    bsplit(x0, hh, ll); khi[base]      = hh; klo[base]      = ll;
    bsplit(x1, hh, ll); khi[base + 64] = hh; klo[base + 64] = ll;
}

// ====================================================================
// bf16 mma.sync GEMM, 3-term split, single-sync pipeline.
// z==2 (V projection) emits bf16 hi/lo directly; else fp32 + bias.
// ====================================================================
#define GBM 128
#define GBN 128
#define GBK 32
#define GKIT (HID / GBK)
#define PITCH 40
#define TILE_B (128 * PITCH * 2)
#define OFF_AHI 0
#define OFF_ALO (1 * TILE_B)
#define OFF_BHI (2 * TILE_B)
#define OFF_BLO (3 * TILE_B)
#define STAGE_B (4 * TILE_B)
#define GEMM_SMEM (2 * STAGE_B)

__global__ __launch_bounds__(256, 2) void gemm_bf16s(
    const __nv_bfloat16* __restrict__ Ahi, const __nv_bfloat16* __restrict__ Alo,
    const __nv_bfloat16* __restrict__ Whi, const __nv_bfloat16* __restrict__ Wlo,
    const float* __restrict__ b0, const float* __restrict__ b1,
    const float* __restrict__ b2,
    float* __restrict__ C0, float* __restrict__ C1,
    __nv_bfloat16* __restrict__ Vhi, __nv_bfloat16* __restrict__ Vlo)
{
    extern __shared__ char sm[];
    const uint32_t sbase = smem_u32(sm);

    const int z = blockIdx.z;
    const __nv_bfloat16* Bhi = Whi + (size_t)z * HID * HID;
    const __nv_bfloat16* Blo = Wlo + (size_t)z * HID * HID;
    const float* bias = (z == 0) ? b0 : (z == 1 ? b1 : b2);

    const int tid  = threadIdx.x;
    const int lane = tid & 31;
    const int wid  = tid >> 5;
    const int wm   = wid & 3;
    const int wn   = wid >> 2;
    const int bm = blockIdx.y * GBM;
    const int bn = blockIdx.x * GBN;

    const int lrow = tid >> 1;
    const int lcol = (tid & 1) * 16;
    const uint32_t sdst = (uint32_t)(lrow * (PITCH * 2) + lcol * 2);
    const __nv_bfloat16* pAhi = Ahi + (size_t)(bm + lrow) * HID + lcol;
    const __nv_bfloat16* pAlo = Alo + (size_t)(bm + lrow) * HID + lcol;
    const __nv_bfloat16* pBhi = Bhi + (size_t)(bn + lrow) * HID + lcol;
    const __nv_bfloat16* pBlo = Blo + (size_t)(bn + lrow) * HID + lcol;

    float acc[2][8][4];
#pragma unroll
    for (int mi = 0; mi < 2; ++mi)
#pragma unroll
        for (int nj = 0; nj < 8; ++nj)
#pragma unroll
            for (int c = 0; c < 4; ++c) acc[mi][nj][c] = 0.f;

    auto load_stage = [&](int kt, int buf) {
        const int k0 = kt * GBK;
        const uint32_t s = sbase + buf * STAGE_B + sdst;
        CPA16(s + OFF_AHI,      pAhi + k0);
        CPA16(s + OFF_AHI + 16, pAhi + k0 + 8);
        CPA16(s + OFF_ALO,      pAlo + k0);
        CPA16(s + OFF_ALO + 16, pAlo + k0 + 8);
        CPA16(s + OFF_BHI,      pBhi + k0);
        CPA16(s + OFF_BHI + 16, pBhi + k0 + 8);
        CPA16(s + OFF_BLO,      pBlo + k0);
        CPA16(s + OFF_BLO + 16, pBlo + k0 + 8);
    };

    load_stage(0, 0);
    asm volatile("cp.async.commit_group;");

    int buf = 0;
    for (int kt = 0; kt < GKIT; ++kt) {
        // stage kt is the only outstanding group
        asm volatile("cp.async.wait_group 0;");
        __syncthreads();   // data visible to all warps; buf^1 readers done
        if (kt + 1 < GKIT) {
            load_stage(kt + 1, buf ^ 1);
            asm volatile("cp.async.commit_group;");
        }

        const uint32_t sA_hi = sbase + buf * STAGE_B + OFF_AHI;
        const uint32_t sA_lo = sbase + buf * STAGE_B + OFF_ALO;
        const uint32_t sB_hi = sbase + buf * STAGE_B + OFF_BHI;
        const uint32_t sB_lo = sbase + buf * STAGE_B + OFF_BLO;

#pragma unroll
        for (int kk = 0; kk < 2; ++kk) {
            uint32_t a_hi[2][4], a_lo[2][4];
            const int r16 = lane & 15;
            const int ksel = lane >> 4;
#pragma unroll
            for (int mi = 0; mi < 2; ++mi) {
                const uint32_t off =
                    (uint32_t)((wm * 32 + mi * 16 + r16) * (PITCH * 2) +
                               (kk * 2 + ksel) * 16);
                LDSM4(a_hi[mi][0], a_hi[mi][1], a_hi[mi][2], a_hi[mi][3],
                      sA_hi + off);
                LDSM4(a_lo[mi][0], a_lo[mi][1], a_lo[mi][2], a_lo[mi][3],
                      sA_lo + off);
            }
            const int q  = lane >> 3;
            const int rr = lane & 7;
#pragma unroll
            for (int a2 = 0; a2 < 4; ++a2) {
                uint32_t bh[4], bl[4];
                const int row = wn * 64 + a2 * 16 + (q >> 1) * 8 + rr;
                const uint32_t off =
                    (uint32_t)(row * (PITCH * 2) + (kk * 2 + (q & 1)) * 16);
                LDSM4(bh[0], bh[1], bh[2], bh[3], sB_hi + off);
                LDSM4(bl[0], bl[1], bl[2], bl[3], sB_lo + off);
#pragma unroll
                for (int mi = 0; mi < 2; ++mi) {
                    MMA_BF16(acc[mi][a2 * 2],     a_hi[mi], bh);
                    MMA_BF16(acc[mi][a2 * 2],     a_hi[mi], bl);
                    MMA_BF16(acc[mi][a2 * 2],     a_lo[mi], bh);
                    MMA_BF16(acc[mi][a2 * 2 + 1], a_hi[mi], bh + 2);
                    MMA_BF16(acc[mi][a2 * 2 + 1], a_hi[mi], bl + 2);
                    MMA_BF16(acc[mi][a2 * 2 + 1], a_lo[mi], bh + 2);
                }
            }
        }
        buf ^= 1;
    }

    const int trow = lane >> 2;
    const int tcol = (lane & 3) * 2;
    if (z == 2) {
#pragma unroll
        for (int mi = 0; mi < 2; ++mi) {
            const int r = bm + wm * 32 + mi * 16 + trow;
#pragma unroll
            for (int nj = 0; nj < 8; ++nj) {
                const int c = bn + wn * 64 + nj * 8 + tcol;
                const float bx = bias[c], by = bias[c + 1];
                __nv_bfloat16 h0, h1, l0, l1;
                bsplit(acc[mi][nj][0] + bx, h0, l0);
                bsplit(acc[mi][nj][1] + by, h1, l1);
                *(uint32_t*)(Vhi + (size_t)r * HID + c) = pack2(h0, h1);
                *(uint32_t*)(Vlo + (size_t)r * HID + c) = pack2(l0, l1);
                bsplit(acc[mi][nj][2] + bx, h0, l0);
                bsplit(acc[mi][nj][3] + by, h1, l1);
                *(uint32_t*)(Vhi + (size_t)(r + 8) * HID + c) = pack2(h0, h1);
                *(uint32_t*)(Vlo + (size_t)(r + 8) * HID + c) = pack2(l0, l1);
            }
        }
    } else {
        float* C = (z == 0) ? C0 : C1;
#pragma unroll
        for (int mi = 0; mi < 2; ++mi) {
            const int r = bm + wm * 32 + mi * 16 + trow;
#pragma unroll
            for (int nj = 0; nj < 8; ++nj) {
                const int c = bn + wn * 64 + nj * 8 + tcol;
                const float bx = bias[c], by = bias[c + 1];
                float2 o;
                o.x = acc[mi][nj][0] + bx; o.y = acc[mi][nj][1] + by;
                *(float2*)(C + (size_t)r * HID + c) = o;
                o.x = acc[mi][nj][2] + bx; o.y = acc[mi][nj][3] + by;
                *(float2*)(C + (size_t)(r + 8) * HID + c) = o;
            }
        }
    }
}

// ====================================================================
// Flash attention on bf16 mma.sync (3xBF16 split), single-sync pipeline,
// long CTAs scheduled first. Writes attn as bf16 hi/lo.
// ====================================================================
#define FP_B 272
#define QTILE_FB (128 * FP_B)
#define KVTILE_FB (64 * FP_B)
#define FKV0 (2 * QTILE_FB)
#define FKSTG (4 * KVTILE_FB)
#define FLASH_SMEM (FKV0 + 2 * FKSTG)

__global__ __launch_bounds__(256, 1) void flash_tc(
    const __nv_bfloat16* __restrict__ qhi, const __nv_bfloat16* __restrict__ qlo,
    const __nv_bfloat16* __restrict__ khi, const __nv_bfloat16* __restrict__ klo,
    const __nv_bfloat16* __restrict__ vhi, const __nv_bfloat16* __restrict__ vlo,
    __nv_bfloat16* __restrict__ Ohi, __nv_bfloat16* __restrict__ Olo)
{
    extern __shared__ char sm[];
    const uint32_t sb = smem_u32(sm);
    const int h  = blockIdx.y;
    const int qb = gridDim.x - 1 - blockIdx.x;   // long CTAs first
    const int q0 = qb * 128;
    const int tid = threadIdx.x, lane = tid & 31, wm = tid >> 5;

    {
        const __nv_bfloat16* ph = qhi + (size_t)q0 * HID + h * DH;
        const __nv_bfloat16* pl = qlo + (size_t)q0 * HID + h * DH;
#pragma unroll
        for (int i = 0; i < 8; ++i) {
            const int idx = tid + i * 256, row = idx >> 4, c = idx & 15;
            const uint32_t d = (uint32_t)(row * FP_B + c * 16);
            CPA16(sb + d,            ph + (size_t)row * HID + c * 8);
            CPA16(sb + QTILE_FB + d, pl + (size_t)row * HID + c * 8);
        }
    }

    auto load_kv = [&](int t, int b) {
        const int j0 = t * 64;
        const uint32_t s = sb + FKV0 + b * FKSTG;
#pragma unroll
        for (int i = 0; i < 4; ++i) {
            const int idx = tid + i * 256, row = idx >> 4, c = idx & 15;
            const uint32_t d = (uint32_t)(row * FP_B + c * 16);
            const size_t g = (size_t)(j0 + row) * HID + h * DH + c * 8;
            CPA16(s + 0 * KVTILE_FB + d, khi + g);
            CPA16(s + 1 * KVTILE_FB + d, klo + g);
            CPA16(s + 2 * KVTILE_FB + d, vhi + g);
            CPA16(s + 3 * KVTILE_FB + d, vlo + g);
        }
    };

    load_kv(0, 0);
    asm volatile("cp.async.commit_group;");

    float o[16][4];
#pragma unroll
    for (int f = 0; f < 16; ++f)
#pragma unroll
        for (int c = 0; c < 4; ++c) o[f][c] = 0.f;
    float m0 = -1e30f, m1 = -1e30f, l0 = 0.f, l1 = 0.f;

    const int ntiles = 2 * qb + 2;
    int buf = 0;
    for (int t = 0; t < ntiles; ++t) {
        asm volatile("cp.async.wait_group 0;");
        __syncthreads();
        if (t + 1 < ntiles) {
            load_kv(t + 1, buf ^ 1);
            asm volatile("cp.async.commit_group;");
        }

        const int j0 = t * 64;
        const uint32_t skh = sb + FKV0 + buf * FKSTG;
        const uint32_t skl = skh + KVTILE_FB;
        const uint32_t svh = skh + 2 * KVTILE_FB;
        const uint32_t svl = skh + 3 * KVTILE_FB;

        if (j0 <= q0 + wm * 16 + 15) {
            float sc[8][4];
#pragma unroll
            for (int nj = 0; nj < 8; ++nj)
#pragma unroll
                for (int c = 0; c < 4; ++c) sc[nj][c] = 0.f;

            const int r16 = lane & 15, ksel = lane >> 4;
            const int qq = lane >> 3, rr = lane & 7;
#pragma unroll
            for (int kk = 0; kk < 8; ++kk) {
                uint32_t ah[4], al[4];
                const uint32_t aoff =
                    (uint32_t)((wm * 16 + r16) * FP_B + (kk * 2 + ksel) * 16);
                LDSM4(ah[0], ah[1], ah[2], ah[3], sb + aoff);
                LDSM4(al[0], al[1], al[2], al[3], sb + QTILE_FB + aoff);
#pragma unroll
                for (int a2 = 0; a2 < 4; ++a2) {
                    uint32_t bh[4], bl[4];
                    const uint32_t boff =
                        (uint32_t)((a2 * 16 + (qq >> 1) * 8 + rr) * FP_B +
                                   (kk * 2 + (qq & 1)) * 16);
                    LDSM4(bh[0], bh[1], bh[2], bh[3], skh + boff);
                    LDSM4(bl[0], bl[1], bl[2], bl[3], skl + boff);
                    MMA_BF16(sc[a2 * 2],     ah, bh);
                    MMA_BF16(sc[a2 * 2],     ah, bl);
                    MMA_BF16(sc[a2 * 2],     al, bh);
                    MMA_BF16(sc[a2 * 2 + 1], ah, bh + 2);
                    MMA_BF16(sc[a2 * 2 + 1], ah, bl + 2);
                    MMA_BF16(sc[a2 * 2 + 1], al, bh + 2);
                }
            }

            const int r0g = q0 + wm * 16 + (lane >> 2);
            const bool needMask = (j0 + 63 > q0 + wm * 16);
#pragma unroll
            for (int nj = 0; nj < 8; ++nj) {
                const int c0 = j0 + nj * 8 + (lane & 3) * 2;
                sc[nj][0] *= ATT_SCALE; sc[nj][1] *= ATT_SCALE;
                sc[nj][2] *= ATT_SCALE; sc[nj][3] *= ATT_SCALE;
                if (needMask) {
                    if (c0     > r0g)     sc[nj][0] = -1e30f;
                    if (c0 + 1 > r0g)     sc[nj][1] = -1e30f;
                    if (c0     > r0g + 8) sc[nj][2] = -1e30f;
                    if (c0 + 1 > r0g + 8) sc[nj][3] = -1e30f;
                }
            }

            float mx0 = -1e30f, mx1 = -1e30f;
#pragma unroll
            for (int nj = 0; nj < 8; ++nj) {
                mx0 = fmaxf(mx0, fmaxf(sc[nj][0], sc[nj][1]));
                mx1 = fmaxf(mx1, fmaxf(sc[nj][2], sc[nj][3]));
            }
            mx0 = fmaxf(mx0, __shfl_xor_sync(0xffffffffu, mx0, 1));
            mx0 = fmaxf(mx0, __shfl_xor_sync(0xffffffffu, mx0, 2));
            mx1 = fmaxf(mx1, __shfl_xor_sync(0xffffffffu, mx1, 1));
            mx1 = fmaxf(mx1, __shfl_xor_sync(0xffffffffu, mx1, 2));
            const float mn0 = fmaxf(m0, mx0), mn1 = fmaxf(m1, mx1);
            const float al0 = __expf(m0 - mn0), al1 = __expf(m1 - mn1);
            float rs0 = 0.f, rs1 = 0.f;
#pragma unroll
            for (int nj = 0; nj < 8; ++nj) {
                sc[nj][0] = __expf(sc[nj][0] - mn0);
                sc[nj][1] = __expf(sc[nj][1] - mn0);
                sc[nj][2] = __expf(sc[nj][2] - mn1);
                sc[nj][3] = __expf(sc[nj][3] - mn1);
                rs0 += sc[nj][0] + sc[nj][1];
                rs1 += sc[nj][2] + sc[nj][3];
            }
            rs0 += __shfl_xor_sync(0xffffffffu, rs0, 1);
            rs0 += __shfl_xor_sync(0xffffffffu, rs0, 2);
            rs1 += __shfl_xor_sync(0xffffffffu, rs1, 1);
            rs1 += __shfl_xor_sync(0xffffffffu, rs1, 2);
            l0 = l0 * al0 + rs0; l1 = l1 * al1 + rs1;
            m0 = mn0; m1 = mn1;
#pragma unroll
            for (int f = 0; f < 16; ++f) {
                o[f][0] *= al0; o[f][1] *= al0;
                o[f][2] *= al1; o[f][3] *= al1;
            }

            uint32_t pfh[4][4], pfl[4][4];
#pragma unroll
            for (int tp = 0; tp < 4; ++tp) {
                const float* f0 = sc[2 * tp];
                const float* f1 = sc[2 * tp + 1];
                __nv_bfloat16 h0, h1, u0, u1;
#pragma unroll
                for (int half = 0; half < 2; ++half) {
                    const float a0 = half ? f1[0] : f0[0];
                    const float a1 = half ? f1[1] : f0[1];
                    const float a2 = half ? f1[2] : f0[2];
                    const float a3 = half ? f1[3] : f0[3];
                    bsplit(a0, h0, u0); bsplit(a1, h1, u1);
                    pfh[tp][half * 2] = pack2(h0, h1);
                    pfl[tp][half * 2] = pack2(u0, u1);
                    bsplit(a2, h0, u0); bsplit(a3, h1, u1);
                    pfh[tp][half * 2 + 1] = pack2(h0, h1);
                    pfl[tp][half * 2 + 1] = pack2(u0, u1);
                }
            }

            const int g = lane >> 3;
#pragma unroll
            for (int ks = 0; ks < 4; ++ks) {
                uint32_t vh[16][2], vl[16][2];
                const int jrow = ks * 16 + (g & 1) * 8 + (lane & 7);
                const uint32_t cb = (uint32_t)((g >> 1) * 16);
#pragma unroll
                for (int n0 = 0; n0 < 8; ++n0) {
                    const uint32_t boff = (uint32_t)(jrow * FP_B + n0 * 32) + cb;
                    LDSM4T(vh[n0 * 2][0], vh[n0 * 2][1],
                           vh[n0 * 2 + 1][0], vh[n0 * 2 + 1][1], svh + boff);
                    LDSM4T(vl[n0 * 2][0], vl[n0 * 2][1],
                           vl[n0 * 2 + 1][0], vl[n0 * 2 + 1][1], svl + boff);
                }
#pragma unroll
                for (int nf = 0; nf < 16; ++nf) {
                    MMA_BF16(o[nf], pfh[ks], vh[nf]);
                    MMA_BF16(o[nf], pfh[ks], vl[nf]);
                    MMA_BF16(o[nf], pfl[ks], vh[nf]);
                }
            }
        }
        buf ^= 1;
    }

    const float i0 = 1.f / l0, i1 = 1.f / l1;
    const int r0g = q0 + wm * 16 + (lane >> 2);
#pragma unroll
    for (int nf = 0; nf < 16; ++nf) {
        const int col = h * DH + nf * 8 + (lane & 3) * 2;
        __nv_bfloat16 h0, h1, u0, u1;
        bsplit(o[nf][0] * i0, h0, u0);
        bsplit(o[nf][1] * i0, h1, u1);
        *(uint32_t*)(Ohi + (size_t)r0g * HID + col) = pack2(h0, h1);
        *(uint32_t*)(Olo + (size_t)r0g * HID + col) = pack2(u0, u1);
        bsplit(o[nf][2] * i1, h0, u0);
        bsplit(o[nf][3] * i1, h1, u1);
        *(uint32_t*)(Ohi + (size_t)(r0g + 8) * HID + col) = pack2(h0, h1);
        *(uint32_t*)(Olo + (size_t)(r0g + 8) * HID + col) = pack2(u0, u1);
    }
}

// ====================================================================
// Residual + LayerNorm.
// ====================================================================
__device__ __forceinline__ float block_sum256(float v, float* red)
{
    __syncthreads();
    const int lane = threadIdx.x & 31;
    const int wp   = threadIdx.x >> 5;
#pragma unroll
    for (int o = 16; o; o >>= 1) v += __shfl_xor_sync(0xffffffffu, v, o);
    if (lane == 0) red[wp] = v;
    __syncthreads();
    if (wp == 0) {
        v = (lane < 8) ? red[lane] : 0.f;
#pragma unroll
        for (int o = 4; o; o >>= 1) v += __shfl_xor_sync(0xffffffffu, v, o);
        if (lane == 0) red[0] = v;
    }
    __syncthreads();
    return red[0];
}

__global__ __launch_bounds__(256) void ln_kernel(
    const float* __restrict__ O, const float* __restrict__ X,
    const float* __restrict__ w, const float* __restrict__ b,
    float* __restrict__ out)
{
    __shared__ float row[HID];
    __shared__ float red[8];
    const int s = blockIdx.x;
    const int tid = threadIdx.x;

    float lsum = 0.f;
    for (int c = tid * 4; c < HID; c += 1024) {
        const float4 o4 = *(const float4*)(O + s * HID + c);
        const float4 x4 = *(const float4*)(X + s * HID + c);
        float4 r;
        r.x = o4.x + x4.x; r.y = o4.y + x4.y;
        r.z = o4.z + x4.z; r.w = o4.w + x4.w;
        *(float4*)&row[c] = r;
        lsum += r.x + r.y + r.z + r.w;
    }
    const float mean = block_sum256(lsum, red) * (1.f / HID);

    float lsq = 0.f;
    for (int c = tid * 4; c < HID; c += 1024) {
        const float4 r = *(const float4*)&row[c];
        const float dx = r.x - mean, dy = r.y - mean;
        const float dz = r.z - mean, dw = r.w - mean;
        lsq += dx * dx + dy * dy + dz * dz + dw * dw;
    }
    const float var  = block_sum256(lsq, red) * (1.f / HID);
    const float rstd = rsqrtf(var + 1e-5f);

    for (int c = tid * 4; c < HID; c += 1024) {
        const float4 r  = *(const float4*)&row[c];
        const float4 w4 = *(const float4*)(w + c);
        const float4 b4 = *(const float4*)(b + c);
        float4 y;
        y.x = (r.x - mean) * rstd * w4.x + b4.x;
        y.y = (r.y - mean) * rstd * w4.y + b4.y;
        y.z = (r.z - mean) * rstd * w4.z + b4.z;
        y.w = (r.w - mean) * rstd * w4.w + b4.w;
        *(float4*)(out + s * HID + c) = y;
    }
}

// ====================================================================
// launch
// ====================================================================
extern "C" void kernel_launch(void* const* d_in, const int* in_sizes, int n_in,
                              void* d_out, int out_size)
{
    const float* x   = (const float*)d_in[0];
    const float* Wq  = (const float*)d_in[1];
    const float* bq  = (const float*)d_in[2];
    const float* Wk  = (const float*)d_in[3];
    const float* bk  = (const float*)d_in[4];
    const float* Wv  = (const float*)d_in[5];
    const float* bv  = (const float*)d_in[6];
    const float* Wo  = (const float*)d_in[7];
    const float* bo  = (const float*)d_in[8];
    const float* lnw = (const float*)d_in[9];
    const float* lnb = (const float*)d_in[10];
    float* out = (float*)d_out;

    float *q, *k, *o;
    __nv_bfloat16 *xhi, *xlo, *whi, *wlo;
    __nv_bfloat16 *qhi, *qlo, *khi, *klo, *vhi, *vlo;
    cudaGetSymbolAddress((void**)&q,    g_q);
    cudaGetSymbolAddress((void**)&k,    g_k);
    cudaGetSymbolAddress((void**)&o,    g_o);
    cudaGetSymbolAddress((void**)&xhi,  g_xhi);
    cudaGetSymbolAddress((void**)&xlo,  g_xlo);
    cudaGetSymbolAddress((void**)&whi,  g_whi);
    cudaGetSymbolAddress((void**)&wlo,  g_wlo);
    cudaGetSymbolAddress((void**)&qhi,  g_qhi);
    cudaGetSymbolAddress((void**)&qlo,  g_qlo);
    cudaGetSymbolAddress((void**)&khi,  g_khi);
    cudaGetSymbolAddress((void**)&klo,  g_klo);
    cudaGetSymbolAddress((void**)&vhi,  g_vhi);
    cudaGetSymbolAddress((void**)&vlo,  g_vlo);

    cudaFuncSetAttribute(gemm_bf16s,
                         cudaFuncAttributeMaxDynamicSharedMemorySize, GEMM_SMEM);
    cudaFuncSetAttribute(flash_tc,
                         cudaFuncAttributeMaxDynamicSharedMemorySize, FLASH_SMEM);

    const int N4  = SEQ * HID / 4;
    const int SGR = N4 / 256;

    // ---- all 5 splits in one launch (x, Wq, Wk, Wv, Wo) ----
    split5_kernel<<<dim3(SGR, 5), 256>>>(x, Wq, Wk, Wv, Wo,
                                         xhi, xlo, whi, wlo, N4);

    // ---- QKV projections (z==2 emits bf16 V directly) ----
    gemm_bf16s<<<dim3(HID / GBN, SEQ / GBM, 3), 256, GEMM_SMEM>>>(
        xhi, xlo, whi, wlo, bq, bk, bv, q, k, vhi, vlo);

    rope_split_kernel<<<SEQ, 1024>>>(q, k, qhi, qlo, khi, klo);

    // ---- flash attention (writes attn as bf16 hi/lo into xhi/xlo) ----
    flash_tc<<<dim3(SEQ / 128, NHEADS), 256, FLASH_SMEM>>>(
        qhi, qlo, khi, klo, vhi, vlo, xhi, xlo);

    // ---- O projection (weights pre-split at slab 3) ----
    gemm_bf16s<<<dim3(HID / GBN, SEQ / GBM, 1), 256, GEMM_SMEM>>>(
        xhi, xlo, whi + 3 * (size_t)HID * HID, wlo + 3 * (size_t)HID * HID,
        bo, bo, bo, o, o, vhi, vlo);

    ln_kernel<<<SEQ, 256>>>(o, x, lnw, lnb, out);
}